// round 9
// baseline (speedup 1.0000x reference)
#include <cuda_runtime.h>
#include <cuda_fp16.h>
#include <cstdint>

// ---------------------------------------------------------------- shapes
#define BB    8
#define CIN   16
#define FD    1024
#define TD    512
#define DD    1024
#define NTOK  512
#define LAY   4
#define MROWS (TD*BB)                 // 4096
#define LOGITS_ELEMS (BB*TD*NTOK)     // 2097152
#define KTOT  DD                      // 1024
#define NSRU  (3*DD)                  // 3072
#define WELEMS ((size_t)(LAY*NSRU + NTOK) * KTOT)

// ---------------------------------------------------------------- scratch
__device__ __half g_Xhi[(size_t)MROWS * DD];       // fp16 hi plane (GEMM A)
__device__ __half g_Xlo[(size_t)MROWS * DD];       // fp16 residual
__device__ float  g_U  [(size_t)MROWS * DD * 4];   // permuted U: [m][d][{xt,fp,rp,pad}]
__device__ __half g_Wh [WELEMS];                   // all weights fp16

// ---------------------------------------------------------------- helpers
__device__ __forceinline__ uint32_t s2u(const void* p) {
    uint32_t a;
    asm("{ .reg .u64 t; cvta.to.shared.u64 t, %1; cvt.u32.u64 %0, t; }"
        : "=r"(a) : "l"(p));
    return a;
}
__device__ __forceinline__ void cpasync16(uint32_t dst, const void* src) {
    asm volatile("cp.async.cg.shared.global [%0], [%1], 16;"
                 :: "r"(dst), "l"(src) : "memory");
}
__device__ __forceinline__ void cp_commit() {
    asm volatile("cp.async.commit_group;" ::: "memory");
}
template <int N>
__device__ __forceinline__ void cp_wait() {
    asm volatile("cp.async.wait_group %0;" :: "n"(N) : "memory");
}
__device__ __forceinline__ void ldm_x4(uint32_t a[4], uint32_t addr) {
    asm volatile("ldmatrix.sync.aligned.m8n8.x4.shared.b16 {%0,%1,%2,%3}, [%4];"
                 : "=r"(a[0]), "=r"(a[1]), "=r"(a[2]), "=r"(a[3]) : "r"(addr));
}
__device__ __forceinline__ void ldm_x2t(uint32_t b[2], uint32_t addr) {
    asm volatile("ldmatrix.sync.aligned.m8n8.x2.trans.shared.b16 {%0,%1}, [%2];"
                 : "=r"(b[0]), "=r"(b[1]) : "r"(addr));
}
__device__ __forceinline__ void mma_f16(float c[4], const uint32_t a[4],
                                        const uint32_t b[2]) {
    asm volatile(
        "mma.sync.aligned.m16n8k16.row.col.f32.f16.f16.f32 "
        "{%0,%1,%2,%3}, {%4,%5,%6,%7}, {%8,%9}, {%0,%1,%2,%3};"
        : "+f"(c[0]), "+f"(c[1]), "+f"(c[2]), "+f"(c[3])
        : "r"(a[0]), "r"(a[1]), "r"(a[2]), "r"(a[3]), "r"(b[0]), "r"(b[1]));
}
__device__ __forceinline__ float ex2f(float x) {
    float r;
    asm("ex2.approx.f32 %0, %1;" : "=f"(r) : "f"(x));
    return r;
}
__device__ __forceinline__ float rcpf(float x) {
    float r;
    asm("rcp.approx.f32 %0, %1;" : "=f"(r) : "f"(x));
    return r;
}

// smem per stage (fp16): A 128x(32+8)h = 10240B, B 32x(128+8)h = 8704B.
#define A_PADB  80
#define B_PADB  272
#define BOFF    10240
#define STAGE_B 18944
#define NSTAGES 4
#define SMEM_GEMM (NSTAGES * STAGE_B)
#define NKITER (KTOT / 32)

// ---------------------------------------------------------------- GEMM
// MODE 0: permuted store into U4[m][d][j], j = n>>10, d = n&1023, no bias.
// MODE 1: bias + (t*B+b)->(b*T+t) row remap, standard [row][N] layout.
__device__ __forceinline__ void load_stage(uint32_t st_base,
                                           const __half* __restrict__ Ah,
                                           const __half* __restrict__ Wh,
                                           int rowBase, int colBase, int kt,
                                           int Nglob, int tid) {
    #pragma unroll
    for (int i = 0; i < 2; ++i) {
        const int q  = tid + i * 256;
        const int ar = q >> 2, ac = q & 3;
        cpasync16(st_base + ar * A_PADB + ac * 16,
                  Ah + (size_t)(rowBase + ar) * KTOT + kt + ac * 8);
        const int br = q >> 4, bc = q & 15;
        cpasync16(st_base + BOFF + br * B_PADB + bc * 16,
                  Wh + (size_t)(kt + br) * Nglob + colBase + bc * 8);
    }
    cp_commit();
}

template <int MODE>
__global__ void __launch_bounds__(256, 2)
gemm_f16(const __half* __restrict__ Ah,
         const __half* __restrict__ Wh,
         float* __restrict__ C, const float* __restrict__ bias, int Nglob) {
    extern __shared__ __align__(16) char smem_raw[];
    const uint32_t sb = s2u(smem_raw);

    const int tid = threadIdx.x;
    const int wid = tid >> 5, lane = tid & 31;
    const int wm = wid & 3, wn = wid >> 2;
    const int rowBase = blockIdx.y * 128;
    const int colBase = blockIdx.x * 128;

    float acc[2][8][4];
    #pragma unroll
    for (int i = 0; i < 2; ++i)
        #pragma unroll
        for (int j = 0; j < 8; ++j)
            #pragma unroll
            for (int k = 0; k < 4; ++k) acc[i][j][k] = 0.0f;

    load_stage(sb,               Ah, Wh, rowBase, colBase, 0,  Nglob, tid);
    load_stage(sb + STAGE_B,     Ah, Wh, rowBase, colBase, 32, Nglob, tid);
    load_stage(sb + 2 * STAGE_B, Ah, Wh, rowBase, colBase, 64, Nglob, tid);

    const int lr = lane & 15;
    const int lc = lane >> 4;

    for (int k = 0; k < NKITER; ++k) {
        if (k + 3 <= NKITER) cp_wait<2>(); else if (k + 2 <= NKITER) cp_wait<1>(); else cp_wait<0>();
        __syncthreads();
        if (k + 3 < NKITER)
            load_stage(sb + ((k + 3) & 3) * STAGE_B, Ah, Wh,
                       rowBase, colBase, (k + 3) * 32, Nglob, tid);

        const uint32_t abase = sb + (k & 3) * STAGE_B;
        const uint32_t bbase = abase + BOFF;

        #pragma unroll
        for (int kk = 0; kk < 2; ++kk) {
            const int arow0 = wm * 32 + lr;
            const int acolB = (kk * 16 + lc * 8) * 2;
            uint32_t a0[2][4], bfr[8][2];
            #pragma unroll
            for (int mt = 0; mt < 2; ++mt)
                ldm_x4(a0[mt], abase + (arow0 + mt * 16) * A_PADB + acolB);
            const int browB = (kk * 16 + lr) * B_PADB;
            #pragma unroll
            for (int nt = 0; nt < 8; ++nt)
                ldm_x2t(bfr[nt], bbase + browB + (wn * 64 + nt * 8) * 2);
            #pragma unroll
            for (int mt = 0; mt < 2; ++mt)
                #pragma unroll
                for (int nt = 0; nt < 8; ++nt)
                    mma_f16(acc[mt][nt], a0[mt], bfr[nt]);
        }
        __syncthreads();
    }

    const int rq = lane >> 2;
    const int cq = (lane & 3) * 2;
    if (MODE == 0) {
        // permuted U4 store: column n -> (j = n>>10, d = n&1023); addr = (m*1024+d)*4 + j
        const int j  = colBase >> 10;
        const int dW = (colBase & 1023) + wn * 64;   // d base for this warp
        #pragma unroll
        for (int mt = 0; mt < 2; ++mt) {
            #pragma unroll
            for (int half = 0; half < 2; ++half) {
                const int m = rowBase + wm * 32 + mt * 16 + half * 8 + rq;
                float* cm = C + (size_t)m * (DD * 4) + j;
                #pragma unroll
                for (int nt = 0; nt < 8; ++nt) {
                    const int d = dW + nt * 8 + cq;
                    cm[(size_t)d * 4]       = acc[mt][nt][half * 2 + 0];
                    cm[(size_t)(d + 1) * 4] = acc[mt][nt][half * 2 + 1];
                }
            }
        }
    } else {
        #pragma unroll
        for (int mt = 0; mt < 2; ++mt) {
            #pragma unroll
            for (int half = 0; half < 2; ++half) {
                const int m = rowBase + wm * 32 + mt * 16 + half * 8 + rq;
                const int orow = (m & (BB - 1)) * TD + (m >> 3);
                float* crow = C + (size_t)orow * Nglob + colBase + wn * 64;
                #pragma unroll
                for (int nt = 0; nt < 8; ++nt) {
                    float2 v;
                    v.x = acc[mt][nt][half * 2 + 0] +
                          bias[colBase + wn * 64 + nt * 8 + cq + 0];
                    v.y = acc[mt][nt][half * 2 + 1] +
                          bias[colBase + wn * 64 + nt * 8 + cq + 1];
                    *(float2*)(crow + nt * 8 + cq) = v;
                }
            }
        }
    }
}

// ---------------------------------------------------------------- splits
__device__ __forceinline__ void f16split(float x, __half& hi, __half& lo) {
    hi = __float2half_rn(x);
    lo = __float2half_rn(x - __half2float(hi));
}

__global__ void split_w(const float* __restrict__ Wsru,
                        const float* __restrict__ Wfc,
                        __half* __restrict__ out) {
    const size_t n4sru = (size_t)LAY * NSRU * KTOT / 4;
    const size_t n4    = WELEMS / 4;
    const size_t i = (size_t)blockIdx.x * blockDim.x + threadIdx.x;
    if (i >= n4) return;
    const float4 x = (i < n4sru) ? ((const float4*)Wsru)[i]
                                 : ((const float4*)Wfc)[i - n4sru];
    __half h[4];
    h[0] = __float2half_rn(x.x);
    h[1] = __float2half_rn(x.y);
    h[2] = __float2half_rn(x.z);
    h[3] = __float2half_rn(x.w);
    ((ulonglong1*)out)[i] = *(ulonglong1*)h;
}

// ---------------------------------------------------------------- conv
__global__ void conv_relu_t(const float* __restrict__ feats,
                            const float* __restrict__ w,
                            const float* __restrict__ bptr,
                            __half* __restrict__ Xhi,
                            __half* __restrict__ Xlo) {
    __shared__ float s[32][33];
    const int tx = threadIdx.x, ty = threadIdx.y;
    const int t = blockIdx.x * 32 + tx;
    const int f = blockIdx.y * 32 + ty;
    const int b = blockIdx.z;

    float acc = bptr[0];
    const float* base = feats + ((size_t)(b * CIN) * FD + f) * TD + t;
    #pragma unroll
    for (int c = 0; c < CIN; ++c)
        acc = fmaf(base[(size_t)c * FD * TD], w[c], acc);
    s[ty][tx] = fmaxf(acc, 0.0f);
    __syncthreads();

    const int t2 = blockIdx.x * 32 + ty;
    const int f2 = blockIdx.y * 32 + tx;
    const float x = s[tx][ty];
    const size_t o = (size_t)(t2 * BB + b) * DD + f2;
    __half h, l;
    f16split(x, h, l);
    Xhi[o] = h;  Xlo[o] = l;
}

// ---------------------------------------------------------------- SRU recurrence
// U pre-permuted: one LDG.128 per step gives {xt, fp, rp}. Register ring
// RD=8 / distance 7. 128 blocks x 64 threads, 1 chain/thread.
#define RD 8

__global__ void __launch_bounds__(64)
sru_rec(const float4* __restrict__ U4,
        __half* __restrict__ Xhi, __half* __restrict__ Xlo,
        const float* __restrict__ v, const float* __restrict__ bb) {
    const int p = blockIdx.x * 64 + threadIdx.x;   // 0..8191
    const int b = p >> 10;
    const int d = p & 1023;

    const float L2E = 1.4426950408889634f;
    const float vf2 = -v[d]      * L2E;
    const float vr2 = -v[DD + d] * L2E;
    const float bfz = -bb[d]      * L2E;
    const float brz = -bb[DD + d] * L2E;

    const float4* u = U4 + (size_t)b * DD + d;   // + t * 8*DD per step
    const size_t us = (size_t)BB * DD;           // float4 elems per t-step
    const size_t xoff = (size_t)b * DD + d;
    __half* xh = Xhi + xoff;
    __half* xl = Xlo + xoff;
    const size_t xs = (size_t)BB * DD;

    float4 uv[RD];
    __half oh[RD], ol[RD];

    #pragma unroll
    for (int i = 0; i < RD - 1; ++i) {
        uv[i] = __ldg(u + (size_t)i * us);
        oh[i] = xh[(size_t)i * xs];
        ol[i] = xl[(size_t)i * xs];
    }

    float c = 0.0f;
    for (int t0 = 0; t0 < TD; t0 += RD) {
        #pragma unroll
        for (int i = 0; i < RD; ++i) {
            const int t = t0 + i;
            const float xtv = uv[i].x;
            const float fpv = uv[i].y;
            const float rpv = uv[i].z;
            const float xov = __half2float(oh[i]) + __half2float(ol[i]);

            const int tp = t + RD - 1;
            if (tp < TD) {
                const int j = (i + RD - 1) & (RD - 1);
                uv[j] = __ldg(u + (size_t)tp * us);
                oh[j] = xh[(size_t)tp * xs];
                ol[j] = xl[(size_t)tp * xs];
            }

            // f-sigmoid (critical chain)
            const float zf = fmaf(vf2, c, fmaf(fpv, -L2E, bfz));
            const float f  = rcpf(1.0f + ex2f(zf));
            c = fmaf(f, c - xtv, xtv);
            // r-sigmoid + readout (off chain)
            const float zr = fmaf(vr2, c, fmaf(rpv, -L2E, brz));
            const float r  = rcpf(1.0f + ex2f(zr));
            const float h  = fmaf(r, c - xov, xov);

            __half hh, hl;
            f16split(h, hh, hl);
            xh[(size_t)t * xs] = hh;
            xl[(size_t)t * xs] = hl;
        }
    }
}

// ---------------------------------------------------------------- lengths tail
__global__ void tail_k(const int* __restrict__ lenbuf, float* outf,
                       long long* outll, int rem) {
    const int i = threadIdx.x;
    if (i >= BB) return;
    const bool in64 = (lenbuf[1] == 0 && lenbuf[3] == 0 &&
                       lenbuf[5] == 0 && lenbuf[7] == 0);
    const long long val = in64 ? (long long)lenbuf[2 * i] : (long long)lenbuf[i];
    const long long h = val >> 1;
    if (rem >= 16)      outll[i] = h;
    else if (rem >= 8)  outf[i]  = (float)h;
}

// ---------------------------------------------------------------- host side
extern "C" void kernel_launch(void* const* d_in, const int* in_sizes, int n_in,
                              void* d_out, int out_size) {
    const float* feats  = (const float*)d_in[0];
    const int*   slen   = (const int*)d_in[1];
    const float* conv_w = (const float*)d_in[2];
    const float* conv_b = (const float*)d_in[3];
    const float* sru_W  = (const float*)d_in[4];
    const float* sru_v  = (const float*)d_in[5];
    const float* sru_b  = (const float*)d_in[6];
    const float* fc_w   = (const float*)d_in[7];
    const float* fc_b   = (const float*)d_in[8];

    float* Up;
    __half *Xhi, *Xlo, *Wh;
    cudaGetSymbolAddress((void**)&Xhi, g_Xhi);
    cudaGetSymbolAddress((void**)&Xlo, g_Xlo);
    cudaGetSymbolAddress((void**)&Up,  g_U);
    cudaGetSymbolAddress((void**)&Wh,  g_Wh);

    cudaFuncSetAttribute(gemm_f16<0>,
                         cudaFuncAttributeMaxDynamicSharedMemorySize, SMEM_GEMM);
    cudaFuncSetAttribute(gemm_f16<1>,
                         cudaFuncAttributeMaxDynamicSharedMemorySize, SMEM_GEMM);

    // 0) all weights -> fp16 once
    {
        const size_t n4 = WELEMS / 4;
        split_w<<<(int)((n4 + 255) / 256), 256>>>(sru_W, fc_w, Wh);
    }

    // 1) conv + relu + transpose + fp16 hi/lo split
    {
        dim3 grid(TD / 32, FD / 32, BB);
        conv_relu_t<<<grid, dim3(32, 32)>>>(feats, conv_w, conv_b, Xhi, Xlo);
    }

    // 2) SRU layers: GEMM (permuted U4 store) + recurrence
    for (int l = 0; l < LAY; ++l) {
        const size_t woff = (size_t)l * KTOT * NSRU;
        gemm_f16<0><<<dim3(NSRU / 128, MROWS / 128), 256, SMEM_GEMM>>>(
            Xhi, Wh + woff, Up, nullptr, NSRU);
        sru_rec<<<128, 64>>>((const float4*)Up, Xhi, Xlo,
                             sru_v + (size_t)l * 2 * DD,
                             sru_b + (size_t)l * 2 * DD);
    }

    // 3) FC (bias + (t,b)->(b,t) remap) into d_out
    {
        const size_t woff = (size_t)LAY * KTOT * NSRU;
        gemm_f16<1><<<dim3(NTOK / 128, MROWS / 128), 256, SMEM_GEMM>>>(
            Xhi, Wh + woff, (float*)d_out, fc_b, NTOK);
    }

    // 4) lengths tail
    {
        const int rem = out_size - LOGITS_ELEMS;
        if (rem > 0) {
            float* outf = (float*)d_out + LOGITS_ELEMS;
            long long* outll = (long long*)((char*)d_out + (size_t)LOGITS_ELEMS * 4);
            tail_k<<<1, 32>>>(slen, outf, outll, rem);
        }
    }
}

// round 10
// speedup vs baseline: 1.5176x; 1.5176x over previous
#include <cuda_runtime.h>
#include <cuda_fp16.h>
#include <cstdint>

// ---------------------------------------------------------------- shapes
#define BB    8
#define CIN   16
#define FD    1024
#define TD    512
#define DD    1024
#define NTOK  512
#define LAY   4
#define MROWS (TD*BB)                 // 4096
#define LOGITS_ELEMS (BB*TD*NTOK)     // 2097152
#define KTOT  DD                      // 1024
#define NSRU  (3*DD)                  // 3072
#define WELEMS ((size_t)(LAY*NSRU + NTOK) * KTOT)

// ---------------------------------------------------------------- scratch
__device__ __half g_Xhi[(size_t)MROWS * DD];   // fp16 hi plane (GEMM A)
__device__ __half g_Xlo[(size_t)MROWS * DD];   // fp16 residual (readout only)
__device__ float  g_U  [(size_t)MROWS * NSRU]; // GEMM out, [m][3*DD]
__device__ __half g_Wh [WELEMS];               // all weights fp16

// ---------------------------------------------------------------- helpers
__device__ __forceinline__ uint32_t s2u(const void* p) {
    uint32_t a;
    asm("{ .reg .u64 t; cvta.to.shared.u64 t, %1; cvt.u32.u64 %0, t; }"
        : "=r"(a) : "l"(p));
    return a;
}
__device__ __forceinline__ void cpasync16(uint32_t dst, const void* src) {
    asm volatile("cp.async.cg.shared.global [%0], [%1], 16;"
                 :: "r"(dst), "l"(src) : "memory");
}
__device__ __forceinline__ void cpasync4(uint32_t dst, const void* src) {
    asm volatile("cp.async.ca.shared.global [%0], [%1], 4;"
                 :: "r"(dst), "l"(src) : "memory");
}
__device__ __forceinline__ void cp_commit() {
    asm volatile("cp.async.commit_group;" ::: "memory");
}
template <int N>
__device__ __forceinline__ void cp_wait() {
    asm volatile("cp.async.wait_group %0;" :: "n"(N) : "memory");
}
__device__ __forceinline__ void ldm_x4(uint32_t a[4], uint32_t addr) {
    asm volatile("ldmatrix.sync.aligned.m8n8.x4.shared.b16 {%0,%1,%2,%3}, [%4];"
                 : "=r"(a[0]), "=r"(a[1]), "=r"(a[2]), "=r"(a[3]) : "r"(addr));
}
__device__ __forceinline__ void ldm_x2t(uint32_t b[2], uint32_t addr) {
    asm volatile("ldmatrix.sync.aligned.m8n8.x2.trans.shared.b16 {%0,%1}, [%2];"
                 : "=r"(b[0]), "=r"(b[1]) : "r"(addr));
}
__device__ __forceinline__ void mma_f16(float c[4], const uint32_t a[4],
                                        const uint32_t b[2]) {
    asm volatile(
        "mma.sync.aligned.m16n8k16.row.col.f32.f16.f16.f32 "
        "{%0,%1,%2,%3}, {%4,%5,%6,%7}, {%8,%9}, {%0,%1,%2,%3};"
        : "+f"(c[0]), "+f"(c[1]), "+f"(c[2]), "+f"(c[3])
        : "r"(a[0]), "r"(a[1]), "r"(a[2]), "r"(a[3]), "r"(b[0]), "r"(b[1]));
}
__device__ __forceinline__ float ex2f(float x) {
    float r;
    asm("ex2.approx.f32 %0, %1;" : "=f"(r) : "f"(x));
    return r;
}
__device__ __forceinline__ float rcpf(float x) {
    float r;
    asm("rcp.approx.f32 %0, %1;" : "=f"(r) : "f"(x));
    return r;
}

// smem per stage (fp16): A 128x(32+8)h = 10240B, B 32x(128+8)h = 8704B.
#define A_PADB  80
#define B_PADB  272
#define BOFF    10240
#define STAGE_B 18944
#define NSTAGES 4
#define SMEM_GEMM (NSTAGES * STAGE_B)
#define NKITER (KTOT / 32)

// ---------------------------------------------------------------- GEMM
// C = A * W, fp16 inputs, fp32 acc. MODE 0: plain store. MODE 1: bias +
// (t*B+b)->(b*T+t) remap.
__device__ __forceinline__ void load_stage(uint32_t st_base,
                                           const __half* __restrict__ Ah,
                                           const __half* __restrict__ Wh,
                                           int rowBase, int colBase, int kt,
                                           int Nglob, int tid) {
    #pragma unroll
    for (int i = 0; i < 2; ++i) {
        const int q  = tid + i * 256;
        const int ar = q >> 2, ac = q & 3;
        cpasync16(st_base + ar * A_PADB + ac * 16,
                  Ah + (size_t)(rowBase + ar) * KTOT + kt + ac * 8);
        const int br = q >> 4, bc = q & 15;
        cpasync16(st_base + BOFF + br * B_PADB + bc * 16,
                  Wh + (size_t)(kt + br) * Nglob + colBase + bc * 8);
    }
    cp_commit();
}

template <int MODE>
__global__ void __launch_bounds__(256, 2)
gemm_f16(const __half* __restrict__ Ah,
         const __half* __restrict__ Wh,
         float* __restrict__ C, const float* __restrict__ bias, int Nglob) {
    extern __shared__ __align__(16) char smem_raw[];
    const uint32_t sb = s2u(smem_raw);

    const int tid = threadIdx.x;
    const int wid = tid >> 5, lane = tid & 31;
    const int wm = wid & 3, wn = wid >> 2;
    const int rowBase = blockIdx.y * 128;
    const int colBase = blockIdx.x * 128;

    float acc[2][8][4];
    #pragma unroll
    for (int i = 0; i < 2; ++i)
        #pragma unroll
        for (int j = 0; j < 8; ++j)
            #pragma unroll
            for (int k = 0; k < 4; ++k) acc[i][j][k] = 0.0f;

    load_stage(sb,               Ah, Wh, rowBase, colBase, 0,  Nglob, tid);
    load_stage(sb + STAGE_B,     Ah, Wh, rowBase, colBase, 32, Nglob, tid);
    load_stage(sb + 2 * STAGE_B, Ah, Wh, rowBase, colBase, 64, Nglob, tid);

    const int lr = lane & 15;
    const int lc = lane >> 4;

    for (int k = 0; k < NKITER; ++k) {
        if (k + 3 <= NKITER) cp_wait<2>(); else if (k + 2 <= NKITER) cp_wait<1>(); else cp_wait<0>();
        __syncthreads();
        if (k + 3 < NKITER)
            load_stage(sb + ((k + 3) & 3) * STAGE_B, Ah, Wh,
                       rowBase, colBase, (k + 3) * 32, Nglob, tid);

        const uint32_t abase = sb + (k & 3) * STAGE_B;
        const uint32_t bbase = abase + BOFF;

        #pragma unroll
        for (int kk = 0; kk < 2; ++kk) {
            const int arow0 = wm * 32 + lr;
            const int acolB = (kk * 16 + lc * 8) * 2;
            uint32_t a0[2][4], bfr[8][2];
            #pragma unroll
            for (int mt = 0; mt < 2; ++mt)
                ldm_x4(a0[mt], abase + (arow0 + mt * 16) * A_PADB + acolB);
            const int browB = (kk * 16 + lr) * B_PADB;
            #pragma unroll
            for (int nt = 0; nt < 8; ++nt)
                ldm_x2t(bfr[nt], bbase + browB + (wn * 64 + nt * 8) * 2);
            #pragma unroll
            for (int mt = 0; mt < 2; ++mt)
                #pragma unroll
                for (int nt = 0; nt < 8; ++nt)
                    mma_f16(acc[mt][nt], a0[mt], bfr[nt]);
        }
        __syncthreads();
    }

    const int rq = lane >> 2;
    const int cq = (lane & 3) * 2;
    #pragma unroll
    for (int mt = 0; mt < 2; ++mt) {
        #pragma unroll
        for (int half = 0; half < 2; ++half) {
            const int m = rowBase + wm * 32 + mt * 16 + half * 8 + rq;
            const int orow = (MODE == 1) ? ((m & (BB - 1)) * TD + (m >> 3)) : m;
            float* crow = C + (size_t)orow * Nglob + colBase + wn * 64;
            #pragma unroll
            for (int nt = 0; nt < 8; ++nt) {
                float2 v;
                v.x = acc[mt][nt][half * 2 + 0];
                v.y = acc[mt][nt][half * 2 + 1];
                if (MODE == 1) {
                    v.x += bias[colBase + wn * 64 + nt * 8 + cq + 0];
                    v.y += bias[colBase + wn * 64 + nt * 8 + cq + 1];
                }
                *(float2*)(crow + nt * 8 + cq) = v;
            }
        }
    }
}

// ---------------------------------------------------------------- splits
__device__ __forceinline__ void f16split(float x, __half& hi, __half& lo) {
    hi = __float2half_rn(x);
    lo = __float2half_rn(x - __half2float(hi));
}

__global__ void split_w(const float* __restrict__ Wsru,
                        const float* __restrict__ Wfc,
                        __half* __restrict__ out) {
    const size_t n4sru = (size_t)LAY * NSRU * KTOT / 4;
    const size_t n4    = WELEMS / 4;
    const size_t i = (size_t)blockIdx.x * blockDim.x + threadIdx.x;
    if (i >= n4) return;
    const float4 x = (i < n4sru) ? ((const float4*)Wsru)[i]
                                 : ((const float4*)Wfc)[i - n4sru];
    __half h[4];
    h[0] = __float2half_rn(x.x);
    h[1] = __float2half_rn(x.y);
    h[2] = __float2half_rn(x.z);
    h[3] = __float2half_rn(x.w);
    ((ulonglong1*)out)[i] = *(ulonglong1*)h;
}

// ---------------------------------------------------------------- conv
__global__ void conv_relu_t(const float* __restrict__ feats,
                            const float* __restrict__ w,
                            const float* __restrict__ bptr,
                            __half* __restrict__ Xhi,
                            __half* __restrict__ Xlo) {
    __shared__ float s[32][33];
    const int tx = threadIdx.x, ty = threadIdx.y;
    const int t = blockIdx.x * 32 + tx;
    const int f = blockIdx.y * 32 + ty;
    const int b = blockIdx.z;

    float acc = bptr[0];
    const float* base = feats + ((size_t)(b * CIN) * FD + f) * TD + t;
    #pragma unroll
    for (int c = 0; c < CIN; ++c)
        acc = fmaf(base[(size_t)c * FD * TD], w[c], acc);
    s[ty][tx] = fmaxf(acc, 0.0f);
    __syncthreads();

    const int t2 = blockIdx.x * 32 + ty;
    const int f2 = blockIdx.y * 32 + tx;
    const float x = s[tx][ty];
    const size_t o = (size_t)(t2 * BB + b) * DD + f2;
    __half h, l;
    f16split(x, h, l);
    Xhi[o] = h;  Xlo[o] = l;
}

// ---------------------------------------------------------------- SRU recurrence
// 1 chain/thread, 128 blocks x 64 thr (best measured config), cp.async smem
// ring depth 16, per-thread groups, no block syncs. Pair trick: even threads
// prefetch the Xhi half2 covering (d, d+1); odd threads the Xlo half2.
#define RD  16
#define RPD 15

__global__ void __launch_bounds__(64)
sru_rec(const float* __restrict__ U,
        __half* __restrict__ Xhi, __half* __restrict__ Xlo,
        const float* __restrict__ v, const float* __restrict__ bb) {
    __shared__ float    sU[3][RD][64];   // xt, fp, rp
    __shared__ uint32_t sH[RD][32];      // Xhi pairs
    __shared__ uint32_t sL[RD][32];      // Xlo pairs

    const int tid = threadIdx.x;
    const int d = blockIdx.x * 64 + tid;
    const int b = blockIdx.y;
    const int pk  = tid >> 1;            // pair index
    const int odd = tid & 1;

    const float L2E = 1.4426950408889634f;
    const float vf2 = -v[d]      * L2E;
    const float vr2 = -v[DD + d] * L2E;
    const float bfz = -bb[d]      * L2E;
    const float brz = -bb[DD + d] * L2E;

    const float* u0 = U + (size_t)b * 3 * DD + d;
    const size_t xoff = (size_t)b * DD + d;
    __half* xh = Xhi + xoff;
    __half* xl = Xlo + xoff;
    const size_t us = (size_t)BB * 3 * DD;
    const size_t xs = (size_t)BB * DD;

    // this thread's pair-fetch source (even->Xhi pair, odd->Xlo pair)
    const __half* psrc = (odd ? Xlo : Xhi) +
                         (size_t)b * DD + blockIdx.x * 64 + 2 * pk;
    const uint32_t pdst0 = odd ? s2u(&sL[0][pk]) : s2u(&sH[0][pk]);

    const uint32_t uB = s2u(&sU[0][0][0]) + tid * 4;
    const uint32_t hB = s2u(&sH[0][0]) + pk * 4;
    const uint32_t lB = s2u(&sL[0][0]) + pk * 4;
    #define USLOT(fld, s) (uB + ((fld) * RD + (s)) * 256)

    #pragma unroll 1
    for (int t = 0; t < RPD; ++t) {
        const float* u = u0 + (size_t)t * us;
        cpasync4(USLOT(0, t), u);
        cpasync4(USLOT(1, t), u + DD);
        cpasync4(USLOT(2, t), u + 2 * DD);
        cpasync4(pdst0 + t * 128, psrc + (size_t)t * xs);
        cp_commit();
    }

    float c = 0.0f;
    #pragma unroll 4
    for (int t = 0; t < TD; ++t) {
        cp_wait<RPD - 1>();
        const int s = t & (RD - 1);
        float xt, fp, rp;
        uint32_t hu, lu;
        asm volatile("ld.shared.f32 %0, [%1];" : "=f"(xt) : "r"(USLOT(0, s)));
        asm volatile("ld.shared.f32 %0, [%1];" : "=f"(fp) : "r"(USLOT(1, s)));
        asm volatile("ld.shared.f32 %0, [%1];" : "=f"(rp) : "r"(USLOT(2, s)));
        asm volatile("ld.shared.b32 %0, [%1];" : "=r"(hu) : "r"(hB + s * 128));
        asm volatile("ld.shared.b32 %0, [%1];" : "=r"(lu) : "r"(lB + s * 128));

        const int tp = t + RPD;
        if (tp < TD) {
            const int sp = tp & (RD - 1);
            const float* u = u0 + (size_t)tp * us;
            cpasync4(USLOT(0, sp), u);
            cpasync4(USLOT(1, sp), u + DD);
            cpasync4(USLOT(2, sp), u + 2 * DD);
            cpasync4(pdst0 + sp * 128, psrc + (size_t)tp * xs);
        }
        cp_commit();

        // f-sigmoid (critical chain)
        const float zf = fmaf(vf2, c, fmaf(fp, -L2E, bfz));
        const float f  = rcpf(1.0f + ex2f(zf));
        c = fmaf(f, c - xt, xt);
        // r-sigmoid + readout (off chain)
        const float zr = fmaf(vr2, c, fmaf(rp, -L2E, brz));
        const float r  = rcpf(1.0f + ex2f(zr));
        const float2 hv = __half22float2(*(__half2*)&hu);
        const float2 lv = __half22float2(*(__half2*)&lu);
        const float xo = (odd ? hv.y : hv.x) + (odd ? lv.y : lv.x);
        const float h = fmaf(r, c - xo, xo);

        __half hh, hl;
        f16split(h, hh, hl);
        xh[(size_t)t * xs] = hh;
        xl[(size_t)t * xs] = hl;
    }
    #undef USLOT
}

// ---------------------------------------------------------------- lengths tail
__global__ void tail_k(const int* __restrict__ lenbuf, float* outf,
                       long long* outll, int rem) {
    const int i = threadIdx.x;
    if (i >= BB) return;
    const bool in64 = (lenbuf[1] == 0 && lenbuf[3] == 0 &&
                       lenbuf[5] == 0 && lenbuf[7] == 0);
    const long long val = in64 ? (long long)lenbuf[2 * i] : (long long)lenbuf[i];
    const long long h = val >> 1;
    if (rem >= 16)      outll[i] = h;
    else if (rem >= 8)  outf[i]  = (float)h;
}

// ---------------------------------------------------------------- host side
extern "C" void kernel_launch(void* const* d_in, const int* in_sizes, int n_in,
                              void* d_out, int out_size) {
    const float* feats  = (const float*)d_in[0];
    const int*   slen   = (const int*)d_in[1];
    const float* conv_w = (const float*)d_in[2];
    const float* conv_b = (const float*)d_in[3];
    const float* sru_W  = (const float*)d_in[4];
    const float* sru_v  = (const float*)d_in[5];
    const float* sru_b  = (const float*)d_in[6];
    const float* fc_w   = (const float*)d_in[7];
    const float* fc_b   = (const float*)d_in[8];

    float* Up;
    __half *Xhi, *Xlo, *Wh;
    cudaGetSymbolAddress((void**)&Xhi, g_Xhi);
    cudaGetSymbolAddress((void**)&Xlo, g_Xlo);
    cudaGetSymbolAddress((void**)&Up,  g_U);
    cudaGetSymbolAddress((void**)&Wh,  g_Wh);

    cudaFuncSetAttribute(gemm_f16<0>,
                         cudaFuncAttributeMaxDynamicSharedMemorySize, SMEM_GEMM);
    cudaFuncSetAttribute(gemm_f16<1>,
                         cudaFuncAttributeMaxDynamicSharedMemorySize, SMEM_GEMM);

    // 0) all weights -> fp16 once
    {
        const size_t n4 = WELEMS / 4;
        split_w<<<(int)((n4 + 255) / 256), 256>>>(sru_W, fc_w, Wh);
    }

    // 1) conv + relu + transpose + fp16 hi/lo split
    {
        dim3 grid(TD / 32, FD / 32, BB);
        conv_relu_t<<<grid, dim3(32, 32)>>>(feats, conv_w, conv_b, Xhi, Xlo);
    }

    // 2) SRU layers
    for (int l = 0; l < LAY; ++l) {
        const size_t woff = (size_t)l * KTOT * NSRU;
        gemm_f16<0><<<dim3(NSRU / 128, MROWS / 128), 256, SMEM_GEMM>>>(
            Xhi, Wh + woff, Up, nullptr, NSRU);
        sru_rec<<<dim3(DD / 64, BB), 64>>>(Up, Xhi, Xlo,
                                           sru_v + (size_t)l * 2 * DD,
                                           sru_b + (size_t)l * 2 * DD);
    }

    // 3) FC (bias + (t,b)->(b,t) remap) into d_out
    {
        const size_t woff = (size_t)LAY * KTOT * NSRU;
        gemm_f16<1><<<dim3(NTOK / 128, MROWS / 128), 256, SMEM_GEMM>>>(
            Xhi, Wh + woff, (float*)d_out, fc_b, NTOK);
    }

    // 4) lengths tail
    {
        const int rem = out_size - LOGITS_ELEMS;
        if (rem > 0) {
            float* outf = (float*)d_out + LOGITS_ELEMS;
            long long* outll = (long long*)((char*)d_out + (size_t)LOGITS_ELEMS * 4);
            tail_k<<<1, 32>>>(slen, outf, outll, rem);
        }
    }
}

// round 11
// speedup vs baseline: 1.5921x; 1.0491x over previous
#include <cuda_runtime.h>
#include <cuda_fp16.h>
#include <cstdint>

// ---------------------------------------------------------------- shapes
#define BB    8
#define CIN   16
#define FD    1024
#define TD    512
#define DD    1024
#define NTOK  512
#define LAY   4
#define MROWS (TD*BB)                 // 4096
#define LOGITS_ELEMS (BB*TD*NTOK)     // 2097152
#define KTOT  DD                      // 1024
#define NSRU  (3*DD)                  // 3072
#define WELEMS ((size_t)(LAY*NSRU + NTOK) * KTOT)   // 13,107,200

// ---------------------------------------------------------------- scratch
__device__ __half g_Xhi[(size_t)MROWS * DD];   // fp16 hi plane (GEMM A)
__device__ __half g_Xlo[(size_t)MROWS * DD];   // fp16 residual (readout only)
__device__ float  g_U  [(size_t)MROWS * NSRU]; // GEMM out, [m][3*DD]
__device__ __half g_Wh [WELEMS];               // all weights fp16

// ---------------------------------------------------------------- helpers
__device__ __forceinline__ uint32_t s2u(const void* p) {
    uint32_t a;
    asm("{ .reg .u64 t; cvta.to.shared.u64 t, %1; cvt.u32.u64 %0, t; }"
        : "=r"(a) : "l"(p));
    return a;
}
__device__ __forceinline__ void cpasync16(uint32_t dst, const void* src) {
    asm volatile("cp.async.cg.shared.global [%0], [%1], 16;"
                 :: "r"(dst), "l"(src) : "memory");
}
__device__ __forceinline__ void cpasync4(uint32_t dst, const void* src) {
    asm volatile("cp.async.ca.shared.global [%0], [%1], 4;"
                 :: "r"(dst), "l"(src) : "memory");
}
__device__ __forceinline__ void cp_commit() {
    asm volatile("cp.async.commit_group;" ::: "memory");
}
template <int N>
__device__ __forceinline__ void cp_wait() {
    asm volatile("cp.async.wait_group %0;" :: "n"(N) : "memory");
}
__device__ __forceinline__ void ldm_x4(uint32_t a[4], uint32_t addr) {
    asm volatile("ldmatrix.sync.aligned.m8n8.x4.shared.b16 {%0,%1,%2,%3}, [%4];"
                 : "=r"(a[0]), "=r"(a[1]), "=r"(a[2]), "=r"(a[3]) : "r"(addr));
}
__device__ __forceinline__ void ldm_x2t(uint32_t b[2], uint32_t addr) {
    asm volatile("ldmatrix.sync.aligned.m8n8.x2.trans.shared.b16 {%0,%1}, [%2];"
                 : "=r"(b[0]), "=r"(b[1]) : "r"(addr));
}
__device__ __forceinline__ void mma_f16(float c[4], const uint32_t a[4],
                                        const uint32_t b[2]) {
    asm volatile(
        "mma.sync.aligned.m16n8k16.row.col.f32.f16.f16.f32 "
        "{%0,%1,%2,%3}, {%4,%5,%6,%7}, {%8,%9}, {%0,%1,%2,%3};"
        : "+f"(c[0]), "+f"(c[1]), "+f"(c[2]), "+f"(c[3])
        : "r"(a[0]), "r"(a[1]), "r"(a[2]), "r"(a[3]), "r"(b[0]), "r"(b[1]));
}
__device__ __forceinline__ float ex2f(float x) {
    float r;
    asm("ex2.approx.f32 %0, %1;" : "=f"(r) : "f"(x));
    return r;
}
__device__ __forceinline__ float rcpf(float x) {
    float r;
    asm("rcp.approx.f32 %0, %1;" : "=f"(r) : "f"(x));
    return r;
}
__device__ __forceinline__ void f16split(float x, __half& hi, __half& lo) {
    hi = __float2half_rn(x);
    lo = __float2half_rn(x - __half2float(hi));
}

// smem per stage (fp16): A 128x(32+8)h = 10240B, B 32x(128+8)h = 8704B.
#define A_PADB  80
#define B_PADB  272
#define BOFF    10240
#define STAGE_B 18944
#define NSTAGES 4
#define SMEM_GEMM (NSTAGES * STAGE_B)
#define NKITER (KTOT / 32)

// ---------------------------------------------------------------- GEMM
// C = A * W, fp16 inputs, fp32 acc. MODE 0: plain store. MODE 1: bias +
// (t*B+b)->(b*T+t) remap.  (unchanged from R10 — known good)
__device__ __forceinline__ void load_stage(uint32_t st_base,
                                           const __half* __restrict__ Ah,
                                           const __half* __restrict__ Wh,
                                           int rowBase, int colBase, int kt,
                                           int Nglob, int tid) {
    #pragma unroll
    for (int i = 0; i < 2; ++i) {
        const int q  = tid + i * 256;
        const int ar = q >> 2, ac = q & 3;
        cpasync16(st_base + ar * A_PADB + ac * 16,
                  Ah + (size_t)(rowBase + ar) * KTOT + kt + ac * 8);
        const int br = q >> 4, bc = q & 15;
        cpasync16(st_base + BOFF + br * B_PADB + bc * 16,
                  Wh + (size_t)(kt + br) * Nglob + colBase + bc * 8);
    }
    cp_commit();
}

template <int MODE>
__global__ void __launch_bounds__(256, 2)
gemm_f16(const __half* __restrict__ Ah,
         const __half* __restrict__ Wh,
         float* __restrict__ C, const float* __restrict__ bias, int Nglob) {
    extern __shared__ __align__(16) char smem_raw[];
    const uint32_t sb = s2u(smem_raw);

    const int tid = threadIdx.x;
    const int wid = tid >> 5, lane = tid & 31;
    const int wm = wid & 3, wn = wid >> 2;
    const int rowBase = blockIdx.y * 128;
    const int colBase = blockIdx.x * 128;

    float acc[2][8][4];
    #pragma unroll
    for (int i = 0; i < 2; ++i)
        #pragma unroll
        for (int j = 0; j < 8; ++j)
            #pragma unroll
            for (int k = 0; k < 4; ++k) acc[i][j][k] = 0.0f;

    load_stage(sb,               Ah, Wh, rowBase, colBase, 0,  Nglob, tid);
    load_stage(sb + STAGE_B,     Ah, Wh, rowBase, colBase, 32, Nglob, tid);
    load_stage(sb + 2 * STAGE_B, Ah, Wh, rowBase, colBase, 64, Nglob, tid);

    const int lr = lane & 15;
    const int lc = lane >> 4;

    for (int k = 0; k < NKITER; ++k) {
        if (k + 3 <= NKITER) cp_wait<2>(); else if (k + 2 <= NKITER) cp_wait<1>(); else cp_wait<0>();
        __syncthreads();
        if (k + 3 < NKITER)
            load_stage(sb + ((k + 3) & 3) * STAGE_B, Ah, Wh,
                       rowBase, colBase, (k + 3) * 32, Nglob, tid);

        const uint32_t abase = sb + (k & 3) * STAGE_B;
        const uint32_t bbase = abase + BOFF;

        #pragma unroll
        for (int kk = 0; kk < 2; ++kk) {
            const int arow0 = wm * 32 + lr;
            const int acolB = (kk * 16 + lc * 8) * 2;
            uint32_t a0[2][4], bfr[8][2];
            #pragma unroll
            for (int mt = 0; mt < 2; ++mt)
                ldm_x4(a0[mt], abase + (arow0 + mt * 16) * A_PADB + acolB);
            const int browB = (kk * 16 + lr) * B_PADB;
            #pragma unroll
            for (int nt = 0; nt < 8; ++nt)
                ldm_x2t(bfr[nt], bbase + browB + (wn * 64 + nt * 8) * 2);
            #pragma unroll
            for (int mt = 0; mt < 2; ++mt)
                #pragma unroll
                for (int nt = 0; nt < 8; ++nt)
                    mma_f16(acc[mt][nt], a0[mt], bfr[nt]);
        }
        __syncthreads();
    }

    const int rq = lane >> 2;
    const int cq = (lane & 3) * 2;
    #pragma unroll
    for (int mt = 0; mt < 2; ++mt) {
        #pragma unroll
        for (int half = 0; half < 2; ++half) {
            const int m = rowBase + wm * 32 + mt * 16 + half * 8 + rq;
            const int orow = (MODE == 1) ? ((m & (BB - 1)) * TD + (m >> 3)) : m;
            float* crow = C + (size_t)orow * Nglob + colBase + wn * 64;
            #pragma unroll
            for (int nt = 0; nt < 8; ++nt) {
                float2 v;
                v.x = acc[mt][nt][half * 2 + 0];
                v.y = acc[mt][nt][half * 2 + 1];
                if (MODE == 1) {
                    v.x += bias[colBase + wn * 64 + nt * 8 + cq + 0];
                    v.y += bias[colBase + wn * 64 + nt * 8 + cq + 1];
                }
                *(float2*)(crow + nt * 8 + cq) = v;
            }
        }
    }
}

// ---------------------------------------------------------------- fused prep
// conv (blocks 0..4095) + weight split (3200 blocks) + lengths tail (1 block)
// run concurrently in one launch: both memory-bound, overlap at the DRAM cap.
#define CONV_BLKS  4096
#define SPLIT_BLKS 3200   // WELEMS/4/1024
#define PREP_BLKS  (CONV_BLKS + SPLIT_BLKS + 1)

__global__ void __launch_bounds__(1024)
prep_all(const float* __restrict__ feats, const float* __restrict__ w,
         const float* __restrict__ bptr,
         __half* __restrict__ Xhi, __half* __restrict__ Xlo,
         const float* __restrict__ Wsru, const float* __restrict__ Wfc,
         __half* __restrict__ Wh,
         const int* __restrict__ lenbuf, float* outf, long long* outll,
         int rem) {
    __shared__ float s[32][33];
    const int blk = blockIdx.x;
    const int tid = threadIdx.x;

    if (blk < CONV_BLKS) {
        // ---- conv + relu + transpose + fp16 hi/lo split ----
        const int tx = tid & 31, ty = tid >> 5;
        const int bx = blk & 15, by = (blk >> 4) & 31, bz = blk >> 9;
        const int t = bx * 32 + tx;
        const int f = by * 32 + ty;
        const int b = bz;

        float acc = bptr[0];
        const float* base = feats + ((size_t)(b * CIN) * FD + f) * TD + t;
        #pragma unroll
        for (int c = 0; c < CIN; ++c)
            acc = fmaf(base[(size_t)c * FD * TD], w[c], acc);
        s[ty][tx] = fmaxf(acc, 0.0f);
        __syncthreads();

        const int t2 = bx * 32 + ty;
        const int f2 = by * 32 + tx;
        const float x = s[tx][ty];
        const size_t o = (size_t)(t2 * BB + b) * DD + f2;
        __half h, l;
        f16split(x, h, l);
        Xhi[o] = h;  Xlo[o] = l;
    } else if (blk < CONV_BLKS + SPLIT_BLKS) {
        // ---- weights fp32 -> fp16 (SRU then FC, concatenated) ----
        const size_t i = (size_t)(blk - CONV_BLKS) * 1024 + tid;
        const size_t n4sru = (size_t)LAY * NSRU * KTOT / 4;
        const float4 x = (i < n4sru) ? ((const float4*)Wsru)[i]
                                     : ((const float4*)Wfc)[i - n4sru];
        __half h[4];
        h[0] = __float2half_rn(x.x);
        h[1] = __float2half_rn(x.y);
        h[2] = __float2half_rn(x.z);
        h[3] = __float2half_rn(x.w);
        ((ulonglong1*)Wh)[i] = *(ulonglong1*)h;
    } else {
        // ---- lengths tail: s_audio_length // 2 ----
        if (tid < BB && rem > 0) {
            const bool in64 = (lenbuf[1] == 0 && lenbuf[3] == 0 &&
                               lenbuf[5] == 0 && lenbuf[7] == 0);
            const long long val = in64 ? (long long)lenbuf[2 * tid]
                                       : (long long)lenbuf[tid];
            const long long hv = val >> 1;
            if (rem >= 16)      outll[tid] = hv;
            else if (rem >= 8)  outf[tid]  = (float)hv;
        }
    }
}

// ---------------------------------------------------------------- SRU recurrence
// Software-pipelined: at step t, loads step t+1's operands and precomputes
// its off-chain terms, so the critical path is only the 48-cyc c-chain.
// cp.async smem ring depth 16, per-thread groups, no block syncs.
// Pair trick: even threads fetch the Xhi half2 pair, odd the Xlo pair.
#define RD  16
#define RPD 15

__global__ void __launch_bounds__(64)
sru_rec(const float* __restrict__ U,
        __half* __restrict__ Xhi, __half* __restrict__ Xlo,
        const float* __restrict__ v, const float* __restrict__ bb) {
    __shared__ float    sU[3][RD][64];   // xt, fp, rp
    __shared__ uint32_t sH[RD][32];      // Xhi pairs
    __shared__ uint32_t sL[RD][32];      // Xlo pairs

    const int tid = threadIdx.x;
    const int d = blockIdx.x * 64 + tid;
    const int b = blockIdx.y;
    const int pk  = tid >> 1;
    const int odd = tid & 1;

    const float L2E = 1.4426950408889634f;
    const float vf2 = -v[d]      * L2E;
    const float vr2 = -v[DD + d] * L2E;
    const float bfz = -bb[d]      * L2E;
    const float brz = -bb[DD + d] * L2E;

    const float* u0 = U + (size_t)b * 3 * DD + d;
    const size_t xoff = (size_t)b * DD + d;
    __half* xh = Xhi + xoff;
    __half* xl = Xlo + xoff;
    const size_t us = (size_t)BB * 3 * DD;
    const size_t xs = (size_t)BB * DD;

    const __half* psrc = (odd ? Xlo : Xhi) +
                         (size_t)b * DD + blockIdx.x * 64 + 2 * pk;
    const uint32_t pdst0 = odd ? s2u(&sL[0][pk]) : s2u(&sH[0][pk]);

    const uint32_t uB = s2u(&sU[0][0][0]) + tid * 4;
    const uint32_t hB = s2u(&sH[0][0]) + pk * 4;
    const uint32_t lB = s2u(&sL[0][0]) + pk * 4;
    #define USLOT(fld, s) (uB + ((fld) * RD + (s)) * 256)

    // prologue: prefetch steps 0..RPD-1 (15 groups)
    #pragma unroll 1
    for (int t = 0; t < RPD; ++t) {
        const float* u = u0 + (size_t)t * us;
        cpasync4(USLOT(0, t), u);
        cpasync4(USLOT(1, t), u + DD);
        cpasync4(USLOT(2, t), u + 2 * DD);
        cpasync4(pdst0 + t * 128, psrc + (size_t)t * xs);
        cp_commit();
    }

    // preload step 0 operands into "cur" registers
    float xt_c, wf_c, wr_c, xo_c;
    {
        cp_wait<RPD - 2>();   // slots 0 and 1 resident
        float fp0, rp0;
        uint32_t hu, lu;
        asm volatile("ld.shared.f32 %0, [%1];" : "=f"(xt_c) : "r"(USLOT(0, 0)));
        asm volatile("ld.shared.f32 %0, [%1];" : "=f"(fp0)  : "r"(USLOT(1, 0)));
        asm volatile("ld.shared.f32 %0, [%1];" : "=f"(rp0)  : "r"(USLOT(2, 0)));
        asm volatile("ld.shared.b32 %0, [%1];" : "=r"(hu) : "r"(hB));
        asm volatile("ld.shared.b32 %0, [%1];" : "=r"(lu) : "r"(lB));
        wf_c = fmaf(fp0, -L2E, bfz);
        wr_c = fmaf(rp0, -L2E, brz);
        const float2 hv = __half22float2(*(__half2*)&hu);
        const float2 lv = __half22float2(*(__half2*)&lu);
        xo_c = (odd ? hv.y : hv.x) + (odd ? lv.y : lv.x);
    }

    float c = 0.0f;
    #pragma unroll 4
    for (int t = 0; t < TD; ++t) {
        // load & pre-reduce step t+1 (off the critical chain)
        float xt_n = 0.0f, wf_n = 0.0f, wr_n = 0.0f, xo_n = 0.0f;
        if (t + 1 < TD) {
            cp_wait<RPD - 2>();          // slot t+1 resident
            const int s1 = (t + 1) & (RD - 1);
            float fp_n, rp_n;
            uint32_t hu, lu;
            asm volatile("ld.shared.f32 %0, [%1];" : "=f"(xt_n) : "r"(USLOT(0, s1)));
            asm volatile("ld.shared.f32 %0, [%1];" : "=f"(fp_n) : "r"(USLOT(1, s1)));
            asm volatile("ld.shared.f32 %0, [%1];" : "=f"(rp_n) : "r"(USLOT(2, s1)));
            asm volatile("ld.shared.b32 %0, [%1];" : "=r"(hu) : "r"(hB + s1 * 128));
            asm volatile("ld.shared.b32 %0, [%1];" : "=r"(lu) : "r"(lB + s1 * 128));
            wf_n = fmaf(fp_n, -L2E, bfz);
            wr_n = fmaf(rp_n, -L2E, brz);
            const float2 hv = __half22float2(*(__half2*)&hu);
            const float2 lv = __half22float2(*(__half2*)&lu);
            xo_n = (odd ? hv.y : hv.x) + (odd ? lv.y : lv.x);
        }

        // prefetch step t+RPD into ring
        const int tp = t + RPD;
        if (tp < TD) {
            const int sp = tp & (RD - 1);
            const float* u = u0 + (size_t)tp * us;
            cpasync4(USLOT(0, sp), u);
            cpasync4(USLOT(1, sp), u + DD);
            cpasync4(USLOT(2, sp), u + 2 * DD);
            cpasync4(pdst0 + sp * 128, psrc + (size_t)tp * xs);
        }
        cp_commit();

        // critical c-chain for step t (operands already in registers)
        const float zf = fmaf(vf2, c, wf_c);
        const float f  = rcpf(1.0f + ex2f(zf));
        c = fmaf(f, c - xt_c, xt_c);
        // r-path + readout (off chain)
        const float zr = fmaf(vr2, c, wr_c);
        const float r  = rcpf(1.0f + ex2f(zr));
        const float h  = fmaf(r, c - xo_c, xo_c);

        __half hh, hl;
        f16split(h, hh, hl);
        xh[(size_t)t * xs] = hh;
        xl[(size_t)t * xs] = hl;

        xt_c = xt_n;  wf_c = wf_n;  wr_c = wr_n;  xo_c = xo_n;
    }
    #undef USLOT
}

// ---------------------------------------------------------------- host side
extern "C" void kernel_launch(void* const* d_in, const int* in_sizes, int n_in,
                              void* d_out, int out_size) {
    const float* feats  = (const float*)d_in[0];
    const int*   slen   = (const int*)d_in[1];
    const float* conv_w = (const float*)d_in[2];
    const float* conv_b = (const float*)d_in[3];
    const float* sru_W  = (const float*)d_in[4];
    const float* sru_v  = (const float*)d_in[5];
    const float* sru_b  = (const float*)d_in[6];
    const float* fc_w   = (const float*)d_in[7];
    const float* fc_b   = (const float*)d_in[8];

    float* Up;
    __half *Xhi, *Xlo, *Wh;
    cudaGetSymbolAddress((void**)&Xhi, g_Xhi);
    cudaGetSymbolAddress((void**)&Xlo, g_Xlo);
    cudaGetSymbolAddress((void**)&Up,  g_U);
    cudaGetSymbolAddress((void**)&Wh,  g_Wh);

    cudaFuncSetAttribute(gemm_f16<0>,
                         cudaFuncAttributeMaxDynamicSharedMemorySize, SMEM_GEMM);
    cudaFuncSetAttribute(gemm_f16<1>,
                         cudaFuncAttributeMaxDynamicSharedMemorySize, SMEM_GEMM);

    // 0+1+4) fused: conv/relu/transpose/split + weight split + lengths tail
    {
        const int rem = out_size - LOGITS_ELEMS;
        float* outf = (float*)d_out + LOGITS_ELEMS;
        long long* outll = (long long*)((char*)d_out + (size_t)LOGITS_ELEMS * 4);
        prep_all<<<PREP_BLKS, 1024>>>(feats, conv_w, conv_b, Xhi, Xlo,
                                      sru_W, fc_w, Wh, slen, outf, outll, rem);
    }

    // 2) SRU layers
    for (int l = 0; l < LAY; ++l) {
        const size_t woff = (size_t)l * KTOT * NSRU;
        gemm_f16<0><<<dim3(NSRU / 128, MROWS / 128), 256, SMEM_GEMM>>>(
            Xhi, Wh + woff, Up, nullptr, NSRU);
        sru_rec<<<dim3(DD / 64, BB), 64>>>(Up, Xhi, Xlo,
                                           sru_v + (size_t)l * 2 * DD,
                                           sru_b + (size_t)l * 2 * DD);
    }

    // 3) FC (bias + (t,b)->(b,t) remap) into d_out
    {
        const size_t woff = (size_t)LAY * KTOT * NSRU;
        gemm_f16<1><<<dim3(NTOK / 128, MROWS / 128), 256, SMEM_GEMM>>>(
            Xhi, Wh + woff, (float*)d_out, fc_b, NTOK);
    }
}

// round 12
// speedup vs baseline: 1.6435x; 1.0323x over previous
#include <cuda_runtime.h>
#include <cuda_fp16.h>
#include <cstdint>

// ---------------------------------------------------------------- shapes
#define BB    8
#define CIN   16
#define FD    1024
#define TD    512
#define DD    1024
#define NTOK  512
#define LAY   4
#define MROWS (TD*BB)                 // 4096
#define LOGITS_ELEMS (BB*TD*NTOK)     // 2097152
#define KTOT  DD                      // 1024
#define NSRU  (3*DD)                  // 3072
#define WELEMS ((size_t)(LAY*NSRU + NTOK) * KTOT)   // 13,107,200

// ---------------------------------------------------------------- scratch
__device__ __half g_Xhi[(size_t)MROWS * DD];   // fp16 hi plane (GEMM A)
__device__ __half g_Xlo[(size_t)MROWS * DD];   // fp16 residual (readout only)
__device__ float  g_U  [(size_t)MROWS * NSRU]; // GEMM out, [m][3*DD]
__device__ __half g_Wh [WELEMS];               // all weights fp16

// ---------------------------------------------------------------- helpers
__device__ __forceinline__ uint32_t s2u(const void* p) {
    uint32_t a;
    asm("{ .reg .u64 t; cvta.to.shared.u64 t, %1; cvt.u32.u64 %0, t; }"
        : "=r"(a) : "l"(p));
    return a;
}
__device__ __forceinline__ void cpasync16(uint32_t dst, const void* src) {
    asm volatile("cp.async.cg.shared.global [%0], [%1], 16;"
                 :: "r"(dst), "l"(src) : "memory");
}
__device__ __forceinline__ void cpasync4(uint32_t dst, const void* src) {
    asm volatile("cp.async.ca.shared.global [%0], [%1], 4;"
                 :: "r"(dst), "l"(src) : "memory");
}
__device__ __forceinline__ void cp_commit() {
    asm volatile("cp.async.commit_group;" ::: "memory");
}
template <int N>
__device__ __forceinline__ void cp_wait() {
    asm volatile("cp.async.wait_group %0;" :: "n"(N) : "memory");
}
__device__ __forceinline__ void ldm_x4(uint32_t a[4], uint32_t addr) {
    asm volatile("ldmatrix.sync.aligned.m8n8.x4.shared.b16 {%0,%1,%2,%3}, [%4];"
                 : "=r"(a[0]), "=r"(a[1]), "=r"(a[2]), "=r"(a[3]) : "r"(addr));
}
__device__ __forceinline__ void ldm_x4t(uint32_t b[4], uint32_t addr) {
    asm volatile("ldmatrix.sync.aligned.m8n8.x4.trans.shared.b16 {%0,%1,%2,%3}, [%4];"
                 : "=r"(b[0]), "=r"(b[1]), "=r"(b[2]), "=r"(b[3]) : "r"(addr));
}
__device__ __forceinline__ void mma_f16(float c[4], const uint32_t a[4],
                                        const uint32_t b[2]) {
    asm volatile(
        "mma.sync.aligned.m16n8k16.row.col.f32.f16.f16.f32 "
        "{%0,%1,%2,%3}, {%4,%5,%6,%7}, {%8,%9}, {%0,%1,%2,%3};"
        : "+f"(c[0]), "+f"(c[1]), "+f"(c[2]), "+f"(c[3])
        : "r"(a[0]), "r"(a[1]), "r"(a[2]), "r"(a[3]), "r"(b[0]), "r"(b[1]));
}
__device__ __forceinline__ float ex2f(float x) {
    float r;
    asm("ex2.approx.f32 %0, %1;" : "=f"(r) : "f"(x));
    return r;
}
__device__ __forceinline__ float rcpf(float x) {
    float r;
    asm("rcp.approx.f32 %0, %1;" : "=f"(r) : "f"(x));
    return r;
}
__device__ __forceinline__ void f16split(float x, __half& hi, __half& lo) {
    hi = __float2half_rn(x);
    lo = __float2half_rn(x - __half2float(hi));
}

// smem per stage (fp16): A 128x(32+8)h = 10240B, B 32x(128+8)h = 8704B.
#define A_PADB  80
#define B_PADB  272
#define BOFF    10240
#define STAGE_B 18944
#define NSTAGES 4
#define SMEM_GEMM (NSTAGES * STAGE_B)
#define NKITER (KTOT / 32)

// ---------------------------------------------------------------- GEMM
// C = A * W, fp16 inputs, fp32 acc. MODE 0: plain store. MODE 1: bias +
// (t*B+b)->(b*T+t) remap. B fragments via ldmatrix.x4.trans; single sync
// per K-tile (4-stage ring makes the bottom barrier redundant).
__device__ __forceinline__ void load_stage(uint32_t st_base,
                                           const __half* __restrict__ Ah,
                                           const __half* __restrict__ Wh,
                                           int rowBase, int colBase, int kt,
                                           int Nglob, int tid) {
    #pragma unroll
    for (int i = 0; i < 2; ++i) {
        const int q  = tid + i * 256;
        const int ar = q >> 2, ac = q & 3;
        cpasync16(st_base + ar * A_PADB + ac * 16,
                  Ah + (size_t)(rowBase + ar) * KTOT + kt + ac * 8);
        const int br = q >> 4, bc = q & 15;
        cpasync16(st_base + BOFF + br * B_PADB + bc * 16,
                  Wh + (size_t)(kt + br) * Nglob + colBase + bc * 8);
    }
    cp_commit();
}

template <int MODE>
__global__ void __launch_bounds__(256, 2)
gemm_f16(const __half* __restrict__ Ah,
         const __half* __restrict__ Wh,
         float* __restrict__ C, const float* __restrict__ bias, int Nglob) {
    extern __shared__ __align__(16) char smem_raw[];
    const uint32_t sb = s2u(smem_raw);

    const int tid = threadIdx.x;
    const int wid = tid >> 5, lane = tid & 31;
    const int wm = wid & 3, wn = wid >> 2;
    const int rowBase = blockIdx.y * 128;
    const int colBase = blockIdx.x * 128;

    float acc[2][8][4];
    #pragma unroll
    for (int i = 0; i < 2; ++i)
        #pragma unroll
        for (int j = 0; j < 8; ++j)
            #pragma unroll
            for (int k = 0; k < 4; ++k) acc[i][j][k] = 0.0f;

    load_stage(sb,               Ah, Wh, rowBase, colBase, 0,  Nglob, tid);
    load_stage(sb + STAGE_B,     Ah, Wh, rowBase, colBase, 32, Nglob, tid);
    load_stage(sb + 2 * STAGE_B, Ah, Wh, rowBase, colBase, 64, Nglob, tid);

    const int lr  = lane & 15;       // A ldsm row select
    const int lc  = lane >> 4;       // A ldsm col-half select
    const int bng = lane >> 4;       // B x4t: n-group select (0/1)

    for (int k = 0; k < NKITER; ++k) {
        if (k + 3 <= NKITER) cp_wait<2>(); else if (k + 2 <= NKITER) cp_wait<1>(); else cp_wait<0>();
        __syncthreads();
        if (k + 3 < NKITER)
            load_stage(sb + ((k + 3) & 3) * STAGE_B, Ah, Wh,
                       rowBase, colBase, (k + 3) * 32, Nglob, tid);

        const uint32_t abase = sb + (k & 3) * STAGE_B;
        const uint32_t bbase = abase + BOFF;

        #pragma unroll
        for (int kk = 0; kk < 2; ++kk) {
            const int arow0 = wm * 32 + lr;
            const int acolB = (kk * 16 + lc * 8) * 2;
            uint32_t a0[2][4], bfr[4][4];
            #pragma unroll
            for (int mt = 0; mt < 2; ++mt)
                ldm_x4(a0[mt], abase + (arow0 + mt * 16) * A_PADB + acolB);
            // x4.trans: lanes 0-15 -> rows k0..k15 of n-group 0, lanes
            // 16-31 -> same rows of n-group 1 (8 cols apart).
            const uint32_t brow = bbase + (kk * 16 + lr) * B_PADB;
            #pragma unroll
            for (int np = 0; np < 4; ++np)
                ldm_x4t(bfr[np], brow + (wn * 64 + np * 16 + bng * 8) * 2);
            #pragma unroll
            for (int mt = 0; mt < 2; ++mt)
                #pragma unroll
                for (int np = 0; np < 4; ++np) {
                    mma_f16(acc[mt][2 * np + 0], a0[mt], &bfr[np][0]);
                    mma_f16(acc[mt][2 * np + 1], a0[mt], &bfr[np][2]);
                }
        }
        // no bottom sync: next iteration's top sync orders stage reuse
        // (stage (k+3)&3 was last read at iteration k-1).
    }

    const int rq = lane >> 2;
    const int cq = (lane & 3) * 2;
    #pragma unroll
    for (int mt = 0; mt < 2; ++mt) {
        #pragma unroll
        for (int half = 0; half < 2; ++half) {
            const int m = rowBase + wm * 32 + mt * 16 + half * 8 + rq;
            const int orow = (MODE == 1) ? ((m & (BB - 1)) * TD + (m >> 3)) : m;
            float* crow = C + (size_t)orow * Nglob + colBase + wn * 64;
            #pragma unroll
            for (int nt = 0; nt < 8; ++nt) {
                float2 v;
                v.x = acc[mt][nt][half * 2 + 0];
                v.y = acc[mt][nt][half * 2 + 1];
                if (MODE == 1) {
                    v.x += bias[colBase + wn * 64 + nt * 8 + cq + 0];
                    v.y += bias[colBase + wn * 64 + nt * 8 + cq + 1];
                }
                *(float2*)(crow + nt * 8 + cq) = v;
            }
        }
    }
}

// ---------------------------------------------------------------- fused prep
#define CONV_BLKS  4096
#define SPLIT_BLKS 3200
#define PREP_BLKS  (CONV_BLKS + SPLIT_BLKS + 1)

__global__ void __launch_bounds__(1024)
prep_all(const float* __restrict__ feats, const float* __restrict__ w,
         const float* __restrict__ bptr,
         __half* __restrict__ Xhi, __half* __restrict__ Xlo,
         const float* __restrict__ Wsru, const float* __restrict__ Wfc,
         __half* __restrict__ Wh,
         const int* __restrict__ lenbuf, float* outf, long long* outll,
         int rem) {
    __shared__ float s[32][33];
    const int blk = blockIdx.x;
    const int tid = threadIdx.x;

    if (blk < CONV_BLKS) {
        const int tx = tid & 31, ty = tid >> 5;
        const int bx = blk & 15, by = (blk >> 4) & 31, bz = blk >> 9;
        const int t = bx * 32 + tx;
        const int f = by * 32 + ty;
        const int b = bz;

        float acc = bptr[0];
        const float* base = feats + ((size_t)(b * CIN) * FD + f) * TD + t;
        #pragma unroll
        for (int c = 0; c < CIN; ++c)
            acc = fmaf(base[(size_t)c * FD * TD], w[c], acc);
        s[ty][tx] = fmaxf(acc, 0.0f);
        __syncthreads();

        const int t2 = bx * 32 + ty;
        const int f2 = by * 32 + tx;
        const float x = s[tx][ty];
        const size_t o = (size_t)(t2 * BB + b) * DD + f2;
        __half h, l;
        f16split(x, h, l);
        Xhi[o] = h;  Xlo[o] = l;
    } else if (blk < CONV_BLKS + SPLIT_BLKS) {
        const size_t i = (size_t)(blk - CONV_BLKS) * 1024 + tid;
        const size_t n4sru = (size_t)LAY * NSRU * KTOT / 4;
        const float4 x = (i < n4sru) ? ((const float4*)Wsru)[i]
                                     : ((const float4*)Wfc)[i - n4sru];
        __half h[4];
        h[0] = __float2half_rn(x.x);
        h[1] = __float2half_rn(x.y);
        h[2] = __float2half_rn(x.z);
        h[3] = __float2half_rn(x.w);
        ((ulonglong1*)Wh)[i] = *(ulonglong1*)h;
    } else {
        if (tid < BB && rem > 0) {
            const bool in64 = (lenbuf[1] == 0 && lenbuf[3] == 0 &&
                               lenbuf[5] == 0 && lenbuf[7] == 0);
            const long long val = in64 ? (long long)lenbuf[2 * tid]
                                       : (long long)lenbuf[tid];
            const long long hv = val >> 1;
            if (rem >= 16)      outll[tid] = hv;
            else if (rem >= 8)  outf[tid]  = (float)hv;
        }
    }
}

// ---------------------------------------------------------------- SRU recurrence
// Software-pipelined; cp.async smem ring depth 16; pair trick for X planes.
#define RD  16
#define RPD 15

__global__ void __launch_bounds__(64)
sru_rec(const float* __restrict__ U,
        __half* __restrict__ Xhi, __half* __restrict__ Xlo,
        const float* __restrict__ v, const float* __restrict__ bb) {
    __shared__ float    sU[3][RD][64];
    __shared__ uint32_t sH[RD][32];
    __shared__ uint32_t sL[RD][32];

    const int tid = threadIdx.x;
    const int d = blockIdx.x * 64 + tid;
    const int b = blockIdx.y;
    const int pk  = tid >> 1;
    const int odd = tid & 1;

    const float L2E = 1.4426950408889634f;
    const float vf2 = -v[d]      * L2E;
    const float vr2 = -v[DD + d] * L2E;
    const float bfz = -bb[d]      * L2E;
    const float brz = -bb[DD + d] * L2E;

    const float* u0 = U + (size_t)b * 3 * DD + d;
    const size_t xoff = (size_t)b * DD + d;
    __half* xh = Xhi + xoff;
    __half* xl = Xlo + xoff;
    const size_t us = (size_t)BB * 3 * DD;
    const size_t xs = (size_t)BB * DD;

    const __half* psrc = (odd ? Xlo : Xhi) +
                         (size_t)b * DD + blockIdx.x * 64 + 2 * pk;
    const uint32_t pdst0 = odd ? s2u(&sL[0][pk]) : s2u(&sH[0][pk]);

    const uint32_t uB = s2u(&sU[0][0][0]) + tid * 4;
    const uint32_t hB = s2u(&sH[0][0]) + pk * 4;
    const uint32_t lB = s2u(&sL[0][0]) + pk * 4;
    #define USLOT(fld, s) (uB + ((fld) * RD + (s)) * 256)

    #pragma unroll 1
    for (int t = 0; t < RPD; ++t) {
        const float* u = u0 + (size_t)t * us;
        cpasync4(USLOT(0, t), u);
        cpasync4(USLOT(1, t), u + DD);
        cpasync4(USLOT(2, t), u + 2 * DD);
        cpasync4(pdst0 + t * 128, psrc + (size_t)t * xs);
        cp_commit();
    }

    float xt_c, wf_c, wr_c, xo_c;
    {
        cp_wait<RPD - 2>();
        float fp0, rp0;
        uint32_t hu, lu;
        asm volatile("ld.shared.f32 %0, [%1];" : "=f"(xt_c) : "r"(USLOT(0, 0)));
        asm volatile("ld.shared.f32 %0, [%1];" : "=f"(fp0)  : "r"(USLOT(1, 0)));
        asm volatile("ld.shared.f32 %0, [%1];" : "=f"(rp0)  : "r"(USLOT(2, 0)));
        asm volatile("ld.shared.b32 %0, [%1];" : "=r"(hu) : "r"(hB));
        asm volatile("ld.shared.b32 %0, [%1];" : "=r"(lu) : "r"(lB));
        wf_c = fmaf(fp0, -L2E, bfz);
        wr_c = fmaf(rp0, -L2E, brz);
        const float2 hv = __half22float2(*(__half2*)&hu);
        const float2 lv = __half22float2(*(__half2*)&lu);
        xo_c = (odd ? hv.y : hv.x) + (odd ? lv.y : lv.x);
    }

    float c = 0.0f;
    #pragma unroll 4
    for (int t = 0; t < TD; ++t) {
        float xt_n = 0.0f, wf_n = 0.0f, wr_n = 0.0f, xo_n = 0.0f;
        if (t + 1 < TD) {
            cp_wait<RPD - 2>();
            const int s1 = (t + 1) & (RD - 1);
            float fp_n, rp_n;
            uint32_t hu, lu;
            asm volatile("ld.shared.f32 %0, [%1];" : "=f"(xt_n) : "r"(USLOT(0, s1)));
            asm volatile("ld.shared.f32 %0, [%1];" : "=f"(fp_n) : "r"(USLOT(1, s1)));
            asm volatile("ld.shared.f32 %0, [%1];" : "=f"(rp_n) : "r"(USLOT(2, s1)));
            asm volatile("ld.shared.b32 %0, [%1];" : "=r"(hu) : "r"(hB + s1 * 128));
            asm volatile("ld.shared.b32 %0, [%1];" : "=r"(lu) : "r"(lB + s1 * 128));
            wf_n = fmaf(fp_n, -L2E, bfz);
            wr_n = fmaf(rp_n, -L2E, brz);
            const float2 hv = __half22float2(*(__half2*)&hu);
            const float2 lv = __half22float2(*(__half2*)&lu);
            xo_n = (odd ? hv.y : hv.x) + (odd ? lv.y : lv.x);
        }

        const int tp = t + RPD;
        if (tp < TD) {
            const int sp = tp & (RD - 1);
            const float* u = u0 + (size_t)tp * us;
            cpasync4(USLOT(0, sp), u);
            cpasync4(USLOT(1, sp), u + DD);
            cpasync4(USLOT(2, sp), u + 2 * DD);
            cpasync4(pdst0 + sp * 128, psrc + (size_t)tp * xs);
        }
        cp_commit();

        const float zf = fmaf(vf2, c, wf_c);
        const float f  = rcpf(1.0f + ex2f(zf));
        c = fmaf(f, c - xt_c, xt_c);
        const float zr = fmaf(vr2, c, wr_c);
        const float r  = rcpf(1.0f + ex2f(zr));
        const float h  = fmaf(r, c - xo_c, xo_c);

        __half hh, hl;
        f16split(h, hh, hl);
        xh[(size_t)t * xs] = hh;
        xl[(size_t)t * xs] = hl;

        xt_c = xt_n;  wf_c = wf_n;  wr_c = wr_n;  xo_c = xo_n;
    }
    #undef USLOT
}

// ---------------------------------------------------------------- host side
extern "C" void kernel_launch(void* const* d_in, const int* in_sizes, int n_in,
                              void* d_out, int out_size) {
    const float* feats  = (const float*)d_in[0];
    const int*   slen   = (const int*)d_in[1];
    const float* conv_w = (const float*)d_in[2];
    const float* conv_b = (const float*)d_in[3];
    const float* sru_W  = (const float*)d_in[4];
    const float* sru_v  = (const float*)d_in[5];
    const float* sru_b  = (const float*)d_in[6];
    const float* fc_w   = (const float*)d_in[7];
    const float* fc_b   = (const float*)d_in[8];

    float* Up;
    __half *Xhi, *Xlo, *Wh;
    cudaGetSymbolAddress((void**)&Xhi, g_Xhi);
    cudaGetSymbolAddress((void**)&Xlo, g_Xlo);
    cudaGetSymbolAddress((void**)&Up,  g_U);
    cudaGetSymbolAddress((void**)&Wh,  g_Wh);

    cudaFuncSetAttribute(gemm_f16<0>,
                         cudaFuncAttributeMaxDynamicSharedMemorySize, SMEM_GEMM);
    cudaFuncSetAttribute(gemm_f16<1>,
                         cudaFuncAttributeMaxDynamicSharedMemorySize, SMEM_GEMM);

    // 0+1+4) fused prep
    {
        const int rem = out_size - LOGITS_ELEMS;
        float* outf = (float*)d_out + LOGITS_ELEMS;
        long long* outll = (long long*)((char*)d_out + (size_t)LOGITS_ELEMS * 4);
        prep_all<<<PREP_BLKS, 1024>>>(feats, conv_w, conv_b, Xhi, Xlo,
                                      sru_W, fc_w, Wh, slen, outf, outll, rem);
    }

    // 2) SRU layers
    for (int l = 0; l < LAY; ++l) {
        const size_t woff = (size_t)l * KTOT * NSRU;
        gemm_f16<0><<<dim3(NSRU / 128, MROWS / 128), 256, SMEM_GEMM>>>(
            Xhi, Wh + woff, Up, nullptr, NSRU);
        sru_rec<<<dim3(DD / 64, BB), 64>>>(Up, Xhi, Xlo,
                                           sru_v + (size_t)l * 2 * DD,
                                           sru_b + (size_t)l * 2 * DD);
    }

    // 3) FC (bias + (t,b)->(b,t) remap) into d_out
    {
        const size_t woff = (size_t)LAY * KTOT * NSRU;
        gemm_f16<1><<<dim3(NTOK / 128, MROWS / 128), 256, SMEM_GEMM>>>(
            Xhi, Wh + woff, (float*)d_out, fc_b, NTOK);
    }
}

// round 13
// speedup vs baseline: 1.9878x; 1.2095x over previous
#include <cuda_runtime.h>
#include <cuda_fp16.h>
#include <cstdint>

// ---------------------------------------------------------------- shapes
#define BB    8
#define CIN   16
#define FD    1024
#define TD    512
#define DD    1024
#define NTOK  512
#define LAY   4
#define MROWS (TD*BB)                 // 4096
#define LOGITS_ELEMS (BB*TD*NTOK)     // 2097152
#define KTOT  DD                      // 1024
#define NSRU  (3*DD)                  // 3072
#define WELEMS ((size_t)(LAY*NSRU + NTOK) * KTOT)   // 13,107,200

// ---------------------------------------------------------------- scratch
__device__ __half g_Xhi[(size_t)MROWS * DD];   // fp16 hi plane (GEMM A)
__device__ __half g_Xlo[(size_t)MROWS * DD];   // fp16 residual (readout only)
__device__ float  g_U  [(size_t)MROWS * NSRU]; // GEMM out, [m][3*DD]
__device__ __half g_Wh [WELEMS];               // all weights fp16

// ---------------------------------------------------------------- helpers
__device__ __forceinline__ uint32_t s2u(const void* p) {
    uint32_t a;
    asm("{ .reg .u64 t; cvta.to.shared.u64 t, %1; cvt.u32.u64 %0, t; }"
        : "=r"(a) : "l"(p));
    return a;
}
__device__ __forceinline__ void cpasync16(uint32_t dst, const void* src) {
    asm volatile("cp.async.cg.shared.global [%0], [%1], 16;"
                 :: "r"(dst), "l"(src) : "memory");
}
__device__ __forceinline__ void cpasync4(uint32_t dst, const void* src) {
    asm volatile("cp.async.ca.shared.global [%0], [%1], 4;"
                 :: "r"(dst), "l"(src) : "memory");
}
__device__ __forceinline__ void cp_commit() {
    asm volatile("cp.async.commit_group;" ::: "memory");
}
template <int N>
__device__ __forceinline__ void cp_wait() {
    asm volatile("cp.async.wait_group %0;" :: "n"(N) : "memory");
}
__device__ __forceinline__ void ldm_x4(uint32_t a[4], uint32_t addr) {
    asm volatile("ldmatrix.sync.aligned.m8n8.x4.shared.b16 {%0,%1,%2,%3}, [%4];"
                 : "=r"(a[0]), "=r"(a[1]), "=r"(a[2]), "=r"(a[3]) : "r"(addr));
}
__device__ __forceinline__ void ldm_x4t(uint32_t b[4], uint32_t addr) {
    asm volatile("ldmatrix.sync.aligned.m8n8.x4.trans.shared.b16 {%0,%1,%2,%3}, [%4];"
                 : "=r"(b[0]), "=r"(b[1]), "=r"(b[2]), "=r"(b[3]) : "r"(addr));
}
__device__ __forceinline__ void mma_f16(float c[4], const uint32_t a[4],
                                        const uint32_t b[2]) {
    asm volatile(
        "mma.sync.aligned.m16n8k16.row.col.f32.f16.f16.f32 "
        "{%0,%1,%2,%3}, {%4,%5,%6,%7}, {%8,%9}, {%0,%1,%2,%3};"
        : "+f"(c[0]), "+f"(c[1]), "+f"(c[2]), "+f"(c[3])
        : "r"(a[0]), "r"(a[1]), "r"(a[2]), "r"(a[3]), "r"(b[0]), "r"(b[1]));
}
__device__ __forceinline__ float ex2f(float x) {
    float r;
    asm("ex2.approx.f32 %0, %1;" : "=f"(r) : "f"(x));
    return r;
}
__device__ __forceinline__ float rcpf(float x) {
    float r;
    asm("rcp.approx.f32 %0, %1;" : "=f"(r) : "f"(x));
    return r;
}
__device__ __forceinline__ void f16split(float x, __half& hi, __half& lo) {
    hi = __float2half_rn(x);
    lo = __float2half_rn(x - __half2float(hi));
}

// smem per stage (fp16): A 128x(32+8)h = 10240B, B 32x(128+8)h = 8704B.
#define A_PADB  80
#define B_PADB  272
#define BOFF    10240
#define STAGE_B 18944
#define NSTAGES 4
#define SMEM_GEMM (NSTAGES * STAGE_B)
#define NKITER (KTOT / 32)

// ---------------------------------------------------------------- GEMM (frozen)
__device__ __forceinline__ void load_stage(uint32_t st_base,
                                           const __half* __restrict__ Ah,
                                           const __half* __restrict__ Wh,
                                           int rowBase, int colBase, int kt,
                                           int Nglob, int tid) {
    #pragma unroll
    for (int i = 0; i < 2; ++i) {
        const int q  = tid + i * 256;
        const int ar = q >> 2, ac = q & 3;
        cpasync16(st_base + ar * A_PADB + ac * 16,
                  Ah + (size_t)(rowBase + ar) * KTOT + kt + ac * 8);
        const int br = q >> 4, bc = q & 15;
        cpasync16(st_base + BOFF + br * B_PADB + bc * 16,
                  Wh + (size_t)(kt + br) * Nglob + colBase + bc * 8);
    }
    cp_commit();
}

template <int MODE>
__global__ void __launch_bounds__(256, 2)
gemm_f16(const __half* __restrict__ Ah,
         const __half* __restrict__ Wh,
         float* __restrict__ C, const float* __restrict__ bias, int Nglob) {
    extern __shared__ __align__(16) char smem_raw[];
    const uint32_t sb = s2u(smem_raw);

    const int tid = threadIdx.x;
    const int wid = tid >> 5, lane = tid & 31;
    const int wm = wid & 3, wn = wid >> 2;
    const int rowBase = blockIdx.y * 128;
    const int colBase = blockIdx.x * 128;

    float acc[2][8][4];
    #pragma unroll
    for (int i = 0; i < 2; ++i)
        #pragma unroll
        for (int j = 0; j < 8; ++j)
            #pragma unroll
            for (int k = 0; k < 4; ++k) acc[i][j][k] = 0.0f;

    load_stage(sb,               Ah, Wh, rowBase, colBase, 0,  Nglob, tid);
    load_stage(sb + STAGE_B,     Ah, Wh, rowBase, colBase, 32, Nglob, tid);
    load_stage(sb + 2 * STAGE_B, Ah, Wh, rowBase, colBase, 64, Nglob, tid);

    const int lr  = lane & 15;
    const int lc  = lane >> 4;
    const int bng = lane >> 4;

    for (int k = 0; k < NKITER; ++k) {
        if (k + 3 <= NKITER) cp_wait<2>(); else if (k + 2 <= NKITER) cp_wait<1>(); else cp_wait<0>();
        __syncthreads();
        if (k + 3 < NKITER)
            load_stage(sb + ((k + 3) & 3) * STAGE_B, Ah, Wh,
                       rowBase, colBase, (k + 3) * 32, Nglob, tid);

        const uint32_t abase = sb + (k & 3) * STAGE_B;
        const uint32_t bbase = abase + BOFF;

        #pragma unroll
        for (int kk = 0; kk < 2; ++kk) {
            const int arow0 = wm * 32 + lr;
            const int acolB = (kk * 16 + lc * 8) * 2;
            uint32_t a0[2][4], bfr[4][4];
            #pragma unroll
            for (int mt = 0; mt < 2; ++mt)
                ldm_x4(a0[mt], abase + (arow0 + mt * 16) * A_PADB + acolB);
            const uint32_t brow = bbase + (kk * 16 + lr) * B_PADB;
            #pragma unroll
            for (int np = 0; np < 4; ++np)
                ldm_x4t(bfr[np], brow + (wn * 64 + np * 16 + bng * 8) * 2);
            #pragma unroll
            for (int mt = 0; mt < 2; ++mt)
                #pragma unroll
                for (int np = 0; np < 4; ++np) {
                    mma_f16(acc[mt][2 * np + 0], a0[mt], &bfr[np][0]);
                    mma_f16(acc[mt][2 * np + 1], a0[mt], &bfr[np][2]);
                }
        }
    }

    const int rq = lane >> 2;
    const int cq = (lane & 3) * 2;
    #pragma unroll
    for (int mt = 0; mt < 2; ++mt) {
        #pragma unroll
        for (int half = 0; half < 2; ++half) {
            const int m = rowBase + wm * 32 + mt * 16 + half * 8 + rq;
            const int orow = (MODE == 1) ? ((m & (BB - 1)) * TD + (m >> 3)) : m;
            float* crow = C + (size_t)orow * Nglob + colBase + wn * 64;
            #pragma unroll
            for (int nt = 0; nt < 8; ++nt) {
                float2 v;
                v.x = acc[mt][nt][half * 2 + 0];
                v.y = acc[mt][nt][half * 2 + 1];
                if (MODE == 1) {
                    v.x += bias[colBase + wn * 64 + nt * 8 + cq + 0];
                    v.y += bias[colBase + wn * 64 + nt * 8 + cq + 1];
                }
                *(float2*)(crow + nt * 8 + cq) = v;
            }
        }
    }
}

// ---------------------------------------------------------------- fused prep
#define CONV_BLKS  4096
#define SPLIT_BLKS 3200
#define PREP_BLKS  (CONV_BLKS + SPLIT_BLKS + 1)

__global__ void __launch_bounds__(1024)
prep_all(const float* __restrict__ feats, const float* __restrict__ w,
         const float* __restrict__ bptr,
         __half* __restrict__ Xhi, __half* __restrict__ Xlo,
         const float* __restrict__ Wsru, const float* __restrict__ Wfc,
         __half* __restrict__ Wh,
         const int* __restrict__ lenbuf, float* outf, long long* outll,
         int rem) {
    __shared__ float s[32][33];
    const int blk = blockIdx.x;
    const int tid = threadIdx.x;

    if (blk < CONV_BLKS) {
        const int tx = tid & 31, ty = tid >> 5;
        const int bx = blk & 15, by = (blk >> 4) & 31, bz = blk >> 9;
        const int t = bx * 32 + tx;
        const int f = by * 32 + ty;
        const int b = bz;

        float acc = bptr[0];
        const float* base = feats + ((size_t)(b * CIN) * FD + f) * TD + t;
        #pragma unroll
        for (int c = 0; c < CIN; ++c)
            acc = fmaf(base[(size_t)c * FD * TD], w[c], acc);
        s[ty][tx] = fmaxf(acc, 0.0f);
        __syncthreads();

        const int t2 = bx * 32 + ty;
        const int f2 = by * 32 + tx;
        const float x = s[tx][ty];
        const size_t o = (size_t)(t2 * BB + b) * DD + f2;
        __half h, l;
        f16split(x, h, l);
        Xhi[o] = h;  Xlo[o] = l;
    } else if (blk < CONV_BLKS + SPLIT_BLKS) {
        const size_t i = (size_t)(blk - CONV_BLKS) * 1024 + tid;
        const size_t n4sru = (size_t)LAY * NSRU * KTOT / 4;
        const float4 x = (i < n4sru) ? ((const float4*)Wsru)[i]
                                     : ((const float4*)Wfc)[i - n4sru];
        __half h[4];
        h[0] = __float2half_rn(x.x);
        h[1] = __float2half_rn(x.y);
        h[2] = __float2half_rn(x.z);
        h[3] = __float2half_rn(x.w);
        ((ulonglong1*)Wh)[i] = *(ulonglong1*)h;
    } else {
        if (tid < BB && rem > 0) {
            const bool in64 = (lenbuf[1] == 0 && lenbuf[3] == 0 &&
                               lenbuf[5] == 0 && lenbuf[7] == 0);
            const long long val = in64 ? (long long)lenbuf[2 * tid]
                                       : (long long)lenbuf[tid];
            const long long hv = val >> 1;
            if (rem >= 16)      outll[tid] = hv;
            else if (rem >= 8)  outf[tid]  = (float)hv;
        }
    }
}

// ---------------------------------------------------------------- SRU recurrence
// Warp-specialized: warps 0-1 = c-chain (1 chain/thread), warps 2-3 = r-path
// + readout (lag one chunk), warps 4-7 = cp.async loaders (2 loads/thr/step).
// Chunked (8 steps) with one __syncthreads per chunk; ring depth 32 slots.
#define CHUNK 8
#define RING  32
#define NCH   (TD / CHUNK)   // 64

__global__ void __launch_bounds__(256)
sru_rec(const float* __restrict__ U,
        __half* __restrict__ Xhi, __half* __restrict__ Xlo,
        const float* __restrict__ v, const float* __restrict__ bb) {
    __shared__ float    sXT[RING][64];
    __shared__ float    sFP[RING][64];
    __shared__ float    sRP[RING][64];
    __shared__ uint32_t sXH[RING][32];
    __shared__ uint32_t sXL[RING][32];
    __shared__ float    sC[2][CHUNK][64];

    const int tid = threadIdx.x;
    const int wid = tid >> 5;
    const int b = blockIdx.y;
    const int dbase = blockIdx.x * 64;
    const size_t us = (size_t)BB * 3 * DD;
    const size_t xs = (size_t)BB * DD;
    const float L2E = 1.4426950408889634f;

    if (wid >= 4) {
        // ===================== loader warps (tid 128..255) =====================
        // 256 loads/step: q<64 xt | q<128 fp | q<192 rp | q<256 X pairs.
        // Thread j handles q0=2j, q1=2j+1 (fixed roles).
        const int j = tid - 128;
        const float* ubase = U + (size_t)b * 3 * DD + dbase;

        const __half* xbase_h = Xhi + (size_t)b * DD + dbase;
        const __half* xbase_l = Xlo + (size_t)b * DD + dbase;

        // resolve the two fixed load descriptors for this thread
        const void* src0;  uint32_t dst0;  // byte base (slot stride added later)
        const void* src1;  uint32_t dst1;
        {
            #pragma unroll
            for (int e = 0; e < 2; ++e) {
                const int q = 2 * j + e;
                const void* s;
                uint32_t dd;
                if (q < 64)       { s = ubase + q;              dd = s2u(&sXT[0][q]); }
                else if (q < 128) { s = ubase + DD + (q - 64);  dd = s2u(&sFP[0][q - 64]); }
                else if (q < 192) { s = ubase + 2 * DD + (q - 128); dd = s2u(&sRP[0][q - 128]); }
                else {
                    const int qp = q - 192;         // 0..63
                    const int pr = qp >> 1;         // pair 0..31
                    if ((qp & 1) == 0) { s = xbase_h + 2 * pr; dd = s2u(&sXH[0][pr]); }
                    else               { s = xbase_l + 2 * pr; dd = s2u(&sXL[0][pr]); }
                }
                if (e == 0) { src0 = s; dst0 = dd; } else { src1 = s; dst1 = dd; }
            }
        }
        const bool p0 = (2 * j)     >= 192;   // src0 strides by xs (half) vs us (float)
        const bool p1 = (2 * j + 1) >= 192;
        const int q0 = 2 * j, q1 = 2 * j + 1;

        // prologue: chunks 0,1
        #pragma unroll 1
        for (int t = 0; t < 2 * CHUNK; ++t) {
            const int s = t & (RING - 1);
            cpasync4(dst0 + s * (q0 < 192 ? 256 : 128),
                     p0 ? (const void*)((const __half*)src0 + (size_t)t * xs)
                        : (const void*)((const float*)src0 + (size_t)t * us));
            cpasync4(dst1 + s * (q1 < 192 ? 256 : 128),
                     p1 ? (const void*)((const __half*)src1 + (size_t)t * xs)
                        : (const void*)((const float*)src1 + (size_t)t * us));
            cp_commit();
        }
        cp_wait<CHUNK>();

        for (int k = 0; k < NCH; ++k) {
            __syncthreads();
            if (k + 2 < NCH) {
                #pragma unroll 1
                for (int i = 0; i < CHUNK; ++i) {
                    const int t = (k + 2) * CHUNK + i;
                    const int s = t & (RING - 1);
                    cpasync4(dst0 + s * (q0 < 192 ? 256 : 128),
                             p0 ? (const void*)((const __half*)src0 + (size_t)t * xs)
                                : (const void*)((const float*)src0 + (size_t)t * us));
                    cpasync4(dst1 + s * (q1 < 192 ? 256 : 128),
                             p1 ? (const void*)((const __half*)src1 + (size_t)t * xs)
                                : (const void*)((const float*)src1 + (size_t)t * us));
                    cp_commit();
                }
                cp_wait<CHUNK>();
            } else {
                cp_wait<0>();
            }
        }
        __syncthreads();   // final drain sync (r processes last chunk)
    } else if (wid < 2) {
        // ===================== c-chain warps (tid 0..63) =====================
        const int ch = tid;
        const int d = dbase + ch;
        const float vf2 = -v[d] * L2E;
        const float bfz = -bb[d] * L2E;

        float c = 0.0f;
        for (int k = 0; k < NCH; ++k) {
            __syncthreads();
            const int t0 = k * CHUNK;
            float xt_c = sXT[t0 & (RING - 1)][ch];
            float wf_c = fmaf(sFP[t0 & (RING - 1)][ch], -L2E, bfz);
            #pragma unroll
            for (int i = 0; i < CHUNK; ++i) {
                float xt_n = 0.0f, wf_n = 0.0f;
                if (i + 1 < CHUNK) {
                    const int s1 = (t0 + i + 1) & (RING - 1);
                    xt_n = sXT[s1][ch];
                    wf_n = fmaf(sFP[s1][ch], -L2E, bfz);
                }
                const float zf = fmaf(vf2, c, wf_c);
                const float f  = rcpf(1.0f + ex2f(zf));
                c = fmaf(f, c - xt_c, xt_c);
                sC[k & 1][i][ch] = c;
                xt_c = xt_n;  wf_c = wf_n;
            }
        }
        __syncthreads();
    } else {
        // ===================== r/readout warps (tid 64..127) =====================
        const int ch = tid - 64;
        const int d = dbase + ch;
        const float vr2 = -v[DD + d] * L2E;
        const float brz = -bb[DD + d] * L2E;
        __half* xh = Xhi + (size_t)b * DD + d;
        __half* xl = Xlo + (size_t)b * DD + d;
        const int odd = ch & 1;
        const int pr = ch >> 1;

        for (int k = 0; k < NCH; ++k) {
            __syncthreads();
            if (k == 0) continue;   // lag one chunk
            const int kk = k - 1, p = kk & 1;
            #pragma unroll
            for (int i = 0; i < CHUNK; ++i) {
                const int t = kk * CHUNK + i;
                const int s = t & (RING - 1);
                const float cc = sC[p][i][ch];
                const float rp = sRP[s][ch];
                const uint32_t hu = sXH[s][pr];
                const uint32_t lu = sXL[s][pr];
                const float2 hv = __half22float2(*(const __half2*)&hu);
                const float2 lv = __half22float2(*(const __half2*)&lu);
                const float xo = (odd ? hv.y : hv.x) + (odd ? lv.y : lv.x);
                const float zr = fmaf(vr2, cc, fmaf(rp, -L2E, brz));
                const float r  = rcpf(1.0f + ex2f(zr));
                const float h  = fmaf(r, cc - xo, xo);
                __half hh, hl;
                f16split(h, hh, hl);
                xh[(size_t)t * xs] = hh;
                xl[(size_t)t * xs] = hl;
            }
        }
        __syncthreads();
        {   // drain: last chunk
            const int kk = NCH - 1, p = kk & 1;
            #pragma unroll
            for (int i = 0; i < CHUNK; ++i) {
                const int t = kk * CHUNK + i;
                const int s = t & (RING - 1);
                const float cc = sC[p][i][ch];
                const float rp = sRP[s][ch];
                const uint32_t hu = sXH[s][pr];
                const uint32_t lu = sXL[s][pr];
                const float2 hv = __half22float2(*(const __half2*)&hu);
                const float2 lv = __half22float2(*(const __half2*)&lu);
                const float xo = (odd ? hv.y : hv.x) + (odd ? lv.y : lv.x);
                const float zr = fmaf(vr2, cc, fmaf(rp, -L2E, brz));
                const float r  = rcpf(1.0f + ex2f(zr));
                const float h  = fmaf(r, cc - xo, xo);
                __half hh, hl;
                f16split(h, hh, hl);
                xh[(size_t)t * xs] = hh;
                xl[(size_t)t * xs] = hl;
            }
        }
        return;
    }
}

// ---------------------------------------------------------------- host side
extern "C" void kernel_launch(void* const* d_in, const int* in_sizes, int n_in,
                              void* d_out, int out_size) {
    const float* feats  = (const float*)d_in[0];
    const int*   slen   = (const int*)d_in[1];
    const float* conv_w = (const float*)d_in[2];
    const float* conv_b = (const float*)d_in[3];
    const float* sru_W  = (const float*)d_in[4];
    const float* sru_v  = (const float*)d_in[5];
    const float* sru_b  = (const float*)d_in[6];
    const float* fc_w   = (const float*)d_in[7];
    const float* fc_b   = (const float*)d_in[8];

    float* Up;
    __half *Xhi, *Xlo, *Wh;
    cudaGetSymbolAddress((void**)&Xhi, g_Xhi);
    cudaGetSymbolAddress((void**)&Xlo, g_Xlo);
    cudaGetSymbolAddress((void**)&Up,  g_U);
    cudaGetSymbolAddress((void**)&Wh,  g_Wh);

    cudaFuncSetAttribute(gemm_f16<0>,
                         cudaFuncAttributeMaxDynamicSharedMemorySize, SMEM_GEMM);
    cudaFuncSetAttribute(gemm_f16<1>,
                         cudaFuncAttributeMaxDynamicSharedMemorySize, SMEM_GEMM);

    // 0+1+4) fused prep
    {
        const int rem = out_size - LOGITS_ELEMS;
        float* outf = (float*)d_out + LOGITS_ELEMS;
        long long* outll = (long long*)((char*)d_out + (size_t)LOGITS_ELEMS * 4);
        prep_all<<<PREP_BLKS, 1024>>>(feats, conv_w, conv_b, Xhi, Xlo,
                                      sru_W, fc_w, Wh, slen, outf, outll, rem);
    }

    // 2) SRU layers
    for (int l = 0; l < LAY; ++l) {
        const size_t woff = (size_t)l * KTOT * NSRU;
        gemm_f16<0><<<dim3(NSRU / 128, MROWS / 128), 256, SMEM_GEMM>>>(
            Xhi, Wh + woff, Up, nullptr, NSRU);
        sru_rec<<<dim3(DD / 64, BB), 256>>>(Up, Xhi, Xlo,
                                            sru_v + (size_t)l * 2 * DD,
                                            sru_b + (size_t)l * 2 * DD);
    }

    // 3) FC (bias + (t,b)->(b,t) remap) into d_out
    {
        const size_t woff = (size_t)LAY * KTOT * NSRU;
        gemm_f16<1><<<dim3(NTOK / 128, MROWS / 128), 256, SMEM_GEMM>>>(
            Xhi, Wh + woff, (float*)d_out, fc_b, NTOK);
    }
}

// round 14
// speedup vs baseline: 2.0253x; 1.0188x over previous
#include <cuda_runtime.h>
#include <cuda_fp16.h>
#include <cstdint>

// ---------------------------------------------------------------- shapes
#define BB    8
#define CIN   16
#define FD    1024
#define TD    512
#define DD    1024
#define NTOK  512
#define LAY   4
#define MROWS (TD*BB)                 // 4096
#define LOGITS_ELEMS (BB*TD*NTOK)     // 2097152
#define KTOT  DD                      // 1024
#define NSRU  (3*DD)                  // 3072
#define WELEMS ((size_t)(LAY*NSRU + NTOK) * KTOT)   // 13,107,200

// ---------------------------------------------------------------- scratch
__device__ __half g_Xhi[(size_t)MROWS * DD];   // fp16 hi plane (GEMM A)
__device__ __half g_Xlo[(size_t)MROWS * DD];   // fp16 residual (readout only)
__device__ float  g_U  [(size_t)MROWS * NSRU]; // GEMM out, [m][3*DD]
__device__ __half g_Wh [WELEMS];               // all weights fp16

// ---------------------------------------------------------------- helpers
__device__ __forceinline__ uint32_t s2u(const void* p) {
    uint32_t a;
    asm("{ .reg .u64 t; cvta.to.shared.u64 t, %1; cvt.u32.u64 %0, t; }"
        : "=r"(a) : "l"(p));
    return a;
}
__device__ __forceinline__ void cpasync16(uint32_t dst, const void* src) {
    asm volatile("cp.async.cg.shared.global [%0], [%1], 16;"
                 :: "r"(dst), "l"(src) : "memory");
}
__device__ __forceinline__ void cpasync4(uint32_t dst, const void* src) {
    asm volatile("cp.async.ca.shared.global [%0], [%1], 4;"
                 :: "r"(dst), "l"(src) : "memory");
}
__device__ __forceinline__ void cp_commit() {
    asm volatile("cp.async.commit_group;" ::: "memory");
}
template <int N>
__device__ __forceinline__ void cp_wait() {
    asm volatile("cp.async.wait_group %0;" :: "n"(N) : "memory");
}
__device__ __forceinline__ void ldm_x4(uint32_t a[4], uint32_t addr) {
    asm volatile("ldmatrix.sync.aligned.m8n8.x4.shared.b16 {%0,%1,%2,%3}, [%4];"
                 : "=r"(a[0]), "=r"(a[1]), "=r"(a[2]), "=r"(a[3]) : "r"(addr));
}
__device__ __forceinline__ void ldm_x4t(uint32_t b[4], uint32_t addr) {
    asm volatile("ldmatrix.sync.aligned.m8n8.x4.trans.shared.b16 {%0,%1,%2,%3}, [%4];"
                 : "=r"(b[0]), "=r"(b[1]), "=r"(b[2]), "=r"(b[3]) : "r"(addr));
}
__device__ __forceinline__ void mma_f16(float c[4], const uint32_t a[4],
                                        const uint32_t b[2]) {
    asm volatile(
        "mma.sync.aligned.m16n8k16.row.col.f32.f16.f16.f32 "
        "{%0,%1,%2,%3}, {%4,%5,%6,%7}, {%8,%9}, {%0,%1,%2,%3};"
        : "+f"(c[0]), "+f"(c[1]), "+f"(c[2]), "+f"(c[3])
        : "r"(a[0]), "r"(a[1]), "r"(a[2]), "r"(a[3]), "r"(b[0]), "r"(b[1]));
}
__device__ __forceinline__ float ex2f(float x) {
    float r;
    asm("ex2.approx.f32 %0, %1;" : "=f"(r) : "f"(x));
    return r;
}
__device__ __forceinline__ float rcpf(float x) {
    float r;
    asm("rcp.approx.f32 %0, %1;" : "=f"(r) : "f"(x));
    return r;
}
__device__ __forceinline__ void f16split(float x, __half& hi, __half& lo) {
    hi = __float2half_rn(x);
    lo = __float2half_rn(x - __half2float(hi));
}

// smem per stage (fp16, BK=64): A 128x(64+8)h = 18432B, B 64x(128+8)h = 17408B.
#define BK      64
#define A_PADB  144    // bytes per A row (64 halves + 8 pad)
#define B_PADB  272    // bytes per B row (128 halves + 8 pad)
#define BOFF    18432
#define STAGE_B 35840
#define NSTAGES 3
#define SMEM_GEMM (NSTAGES * STAGE_B)   // 107520
#define NKITER (KTOT / BK)              // 16

// ---------------------------------------------------------------- GEMM
// C = A * W, fp16 inputs, fp32 acc. BK=64 / 3 stages: 16 barrier regions,
// 4 independent ldsm->MMA groups per region for latency hiding.
__device__ __forceinline__ void load_stage(uint32_t st_base,
                                           const __half* __restrict__ Ah,
                                           const __half* __restrict__ Wh,
                                           int rowBase, int colBase, int kt,
                                           int Nglob, int tid) {
    #pragma unroll
    for (int i = 0; i < 4; ++i) {
        const int q = tid + i * 256;         // 0..1023
        const int ar = q >> 3, ac = q & 7;   // A: 128 rows x 8 x 16B
        cpasync16(st_base + ar * A_PADB + ac * 16,
                  Ah + (size_t)(rowBase + ar) * KTOT + kt + ac * 8);
        const int br = q >> 4, bc = q & 15;  // B: 64 rows x 16 x 16B
        cpasync16(st_base + BOFF + br * B_PADB + bc * 16,
                  Wh + (size_t)(kt + br) * Nglob + colBase + bc * 8);
    }
    cp_commit();
}

template <int MODE>
__global__ void __launch_bounds__(256, 2)
gemm_f16(const __half* __restrict__ Ah,
         const __half* __restrict__ Wh,
         float* __restrict__ C, const float* __restrict__ bias, int Nglob) {
    extern __shared__ __align__(16) char smem_raw[];
    const uint32_t sb = s2u(smem_raw);

    const int tid = threadIdx.x;
    const int wid = tid >> 5, lane = tid & 31;
    const int wm = wid & 3, wn = wid >> 2;
    const int rowBase = blockIdx.y * 128;
    const int colBase = blockIdx.x * 128;

    float acc[2][8][4];
    #pragma unroll
    for (int i = 0; i < 2; ++i)
        #pragma unroll
        for (int j = 0; j < 8; ++j)
            #pragma unroll
            for (int k = 0; k < 4; ++k) acc[i][j][k] = 0.0f;

    load_stage(sb,           Ah, Wh, rowBase, colBase, 0,  Nglob, tid);
    load_stage(sb + STAGE_B, Ah, Wh, rowBase, colBase, BK, Nglob, tid);

    const int lr  = lane & 15;
    const int lc  = lane >> 4;
    const int bng = lane >> 4;

    int st = 0;
    for (int k = 0; k < NKITER; ++k) {
        if (k + 2 <= NKITER) cp_wait<1>(); else cp_wait<0>();
        __syncthreads();
        if (k + 2 < NKITER)
            load_stage(sb + ((st + 2) % 3) * STAGE_B, Ah, Wh,
                       rowBase, colBase, (k + 2) * BK, Nglob, tid);

        const uint32_t abase = sb + st * STAGE_B;
        const uint32_t bbase = abase + BOFF;

        #pragma unroll
        for (int kk = 0; kk < 4; ++kk) {
            const int arow0 = wm * 32 + lr;
            const int acolB = (kk * 16 + lc * 8) * 2;
            uint32_t a0[2][4], bfr[4][4];
            #pragma unroll
            for (int mt = 0; mt < 2; ++mt)
                ldm_x4(a0[mt], abase + (arow0 + mt * 16) * A_PADB + acolB);
            const uint32_t brow = bbase + (kk * 16 + lr) * B_PADB;
            #pragma unroll
            for (int np = 0; np < 4; ++np)
                ldm_x4t(bfr[np], brow + (wn * 64 + np * 16 + bng * 8) * 2);
            #pragma unroll
            for (int mt = 0; mt < 2; ++mt)
                #pragma unroll
                for (int np = 0; np < 4; ++np) {
                    mma_f16(acc[mt][2 * np + 0], a0[mt], &bfr[np][0]);
                    mma_f16(acc[mt][2 * np + 1], a0[mt], &bfr[np][2]);
                }
        }
        st = (st + 1) % 3;
        // no bottom sync: stage written at iter k ((st+2)) was last read at
        // iter k-1; the top sync of iter k orders it.
    }

    const int rq = lane >> 2;
    const int cq = (lane & 3) * 2;
    #pragma unroll
    for (int mt = 0; mt < 2; ++mt) {
        #pragma unroll
        for (int half = 0; half < 2; ++half) {
            const int m = rowBase + wm * 32 + mt * 16 + half * 8 + rq;
            const int orow = (MODE == 1) ? ((m & (BB - 1)) * TD + (m >> 3)) : m;
            float* crow = C + (size_t)orow * Nglob + colBase + wn * 64;
            #pragma unroll
            for (int nt = 0; nt < 8; ++nt) {
                float2 v;
                v.x = acc[mt][nt][half * 2 + 0];
                v.y = acc[mt][nt][half * 2 + 1];
                if (MODE == 1) {
                    v.x += bias[colBase + wn * 64 + nt * 8 + cq + 0];
                    v.y += bias[colBase + wn * 64 + nt * 8 + cq + 1];
                }
                *(float2*)(crow + nt * 8 + cq) = v;
            }
        }
    }
}

// ---------------------------------------------------------------- fused prep
#define CONV_BLKS  4096
#define SPLIT_BLKS 3200
#define PREP_BLKS  (CONV_BLKS + SPLIT_BLKS + 1)

__global__ void __launch_bounds__(1024)
prep_all(const float* __restrict__ feats, const float* __restrict__ w,
         const float* __restrict__ bptr,
         __half* __restrict__ Xhi, __half* __restrict__ Xlo,
         const float* __restrict__ Wsru, const float* __restrict__ Wfc,
         __half* __restrict__ Wh,
         const int* __restrict__ lenbuf, float* outf, long long* outll,
         int rem) {
    __shared__ float s[32][33];
    const int blk = blockIdx.x;
    const int tid = threadIdx.x;

    if (blk < CONV_BLKS) {
        const int tx = tid & 31, ty = tid >> 5;
        const int bx = blk & 15, by = (blk >> 4) & 31, bz = blk >> 9;
        const int t = bx * 32 + tx;
        const int f = by * 32 + ty;
        const int b = bz;

        float acc = bptr[0];
        const float* base = feats + ((size_t)(b * CIN) * FD + f) * TD + t;
        #pragma unroll
        for (int c = 0; c < CIN; ++c)
            acc = fmaf(base[(size_t)c * FD * TD], w[c], acc);
        s[ty][tx] = fmaxf(acc, 0.0f);
        __syncthreads();

        const int t2 = bx * 32 + ty;
        const int f2 = by * 32 + tx;
        const float x = s[tx][ty];
        const size_t o = (size_t)(t2 * BB + b) * DD + f2;
        __half h, l;
        f16split(x, h, l);
        Xhi[o] = h;  Xlo[o] = l;
    } else if (blk < CONV_BLKS + SPLIT_BLKS) {
        const size_t i = (size_t)(blk - CONV_BLKS) * 1024 + tid;
        const size_t n4sru = (size_t)LAY * NSRU * KTOT / 4;
        const float4 x = (i < n4sru) ? ((const float4*)Wsru)[i]
                                     : ((const float4*)Wfc)[i - n4sru];
        __half h[4];
        h[0] = __float2half_rn(x.x);
        h[1] = __float2half_rn(x.y);
        h[2] = __float2half_rn(x.z);
        h[3] = __float2half_rn(x.w);
        ((ulonglong1*)Wh)[i] = *(ulonglong1*)h;
    } else {
        if (tid < BB && rem > 0) {
            const bool in64 = (lenbuf[1] == 0 && lenbuf[3] == 0 &&
                               lenbuf[5] == 0 && lenbuf[7] == 0);
            const long long val = in64 ? (long long)lenbuf[2 * tid]
                                       : (long long)lenbuf[tid];
            const long long hv = val >> 1;
            if (rem >= 16)      outll[tid] = hv;
            else if (rem >= 8)  outf[tid]  = (float)hv;
        }
    }
}

// ---------------------------------------------------------------- SRU recurrence
// Warp-specialized (frozen from R13): warps 0-1 c-chain, 2-3 r/readout,
// 4-7 cp.async loaders; chunked ring.
#define CHUNK 8
#define RING  32
#define NCH   (TD / CHUNK)   // 64

__global__ void __launch_bounds__(256)
sru_rec(const float* __restrict__ U,
        __half* __restrict__ Xhi, __half* __restrict__ Xlo,
        const float* __restrict__ v, const float* __restrict__ bb) {
    __shared__ float    sXT[RING][64];
    __shared__ float    sFP[RING][64];
    __shared__ float    sRP[RING][64];
    __shared__ uint32_t sXH[RING][32];
    __shared__ uint32_t sXL[RING][32];
    __shared__ float    sC[2][CHUNK][64];

    const int tid = threadIdx.x;
    const int wid = tid >> 5;
    const int b = blockIdx.y;
    const int dbase = blockIdx.x * 64;
    const size_t us = (size_t)BB * 3 * DD;
    const size_t xs = (size_t)BB * DD;
    const float L2E = 1.4426950408889634f;

    if (wid >= 4) {
        const int j = tid - 128;
        const float* ubase = U + (size_t)b * 3 * DD + dbase;
        const __half* xbase_h = Xhi + (size_t)b * DD + dbase;
        const __half* xbase_l = Xlo + (size_t)b * DD + dbase;

        const void* src0;  uint32_t dst0;
        const void* src1;  uint32_t dst1;
        {
            #pragma unroll
            for (int e = 0; e < 2; ++e) {
                const int q = 2 * j + e;
                const void* s;
                uint32_t dd;
                if (q < 64)       { s = ubase + q;              dd = s2u(&sXT[0][q]); }
                else if (q < 128) { s = ubase + DD + (q - 64);  dd = s2u(&sFP[0][q - 64]); }
                else if (q < 192) { s = ubase + 2 * DD + (q - 128); dd = s2u(&sRP[0][q - 128]); }
                else {
                    const int qp = q - 192;
                    const int pr = qp >> 1;
                    if ((qp & 1) == 0) { s = xbase_h + 2 * pr; dd = s2u(&sXH[0][pr]); }
                    else               { s = xbase_l + 2 * pr; dd = s2u(&sXL[0][pr]); }
                }
                if (e == 0) { src0 = s; dst0 = dd; } else { src1 = s; dst1 = dd; }
            }
        }
        const bool p0 = (2 * j)     >= 192;
        const bool p1 = (2 * j + 1) >= 192;
        const int q0 = 2 * j, q1 = 2 * j + 1;

        #pragma unroll 1
        for (int t = 0; t < 2 * CHUNK; ++t) {
            const int s = t & (RING - 1);
            cpasync4(dst0 + s * (q0 < 192 ? 256 : 128),
                     p0 ? (const void*)((const __half*)src0 + (size_t)t * xs)
                        : (const void*)((const float*)src0 + (size_t)t * us));
            cpasync4(dst1 + s * (q1 < 192 ? 256 : 128),
                     p1 ? (const void*)((const __half*)src1 + (size_t)t * xs)
                        : (const void*)((const float*)src1 + (size_t)t * us));
            cp_commit();
        }
        cp_wait<CHUNK>();

        for (int k = 0; k < NCH; ++k) {
            __syncthreads();
            if (k + 2 < NCH) {
                #pragma unroll 1
                for (int i = 0; i < CHUNK; ++i) {
                    const int t = (k + 2) * CHUNK + i;
                    const int s = t & (RING - 1);
                    cpasync4(dst0 + s * (q0 < 192 ? 256 : 128),
                             p0 ? (const void*)((const __half*)src0 + (size_t)t * xs)
                                : (const void*)((const float*)src0 + (size_t)t * us));
                    cpasync4(dst1 + s * (q1 < 192 ? 256 : 128),
                             p1 ? (const void*)((const __half*)src1 + (size_t)t * xs)
                                : (const void*)((const float*)src1 + (size_t)t * us));
                    cp_commit();
                }
                cp_wait<CHUNK>();
            } else {
                cp_wait<0>();
            }
        }
        __syncthreads();
    } else if (wid < 2) {
        const int ch = tid;
        const int d = dbase + ch;
        const float vf2 = -v[d] * L2E;
        const float bfz = -bb[d] * L2E;

        float c = 0.0f;
        for (int k = 0; k < NCH; ++k) {
            __syncthreads();
            const int t0 = k * CHUNK;
            float xt_c = sXT[t0 & (RING - 1)][ch];
            float wf_c = fmaf(sFP[t0 & (RING - 1)][ch], -L2E, bfz);
            #pragma unroll
            for (int i = 0; i < CHUNK; ++i) {
                float xt_n = 0.0f, wf_n = 0.0f;
                if (i + 1 < CHUNK) {
                    const int s1 = (t0 + i + 1) & (RING - 1);
                    xt_n = sXT[s1][ch];
                    wf_n = fmaf(sFP[s1][ch], -L2E, bfz);
                }
                const float zf = fmaf(vf2, c, wf_c);
                const float f  = rcpf(1.0f + ex2f(zf));
                c = fmaf(f, c - xt_c, xt_c);
                sC[k & 1][i][ch] = c;
                xt_c = xt_n;  wf_c = wf_n;
            }
        }
        __syncthreads();
    } else {
        const int ch = tid - 64;
        const int d = dbase + ch;
        const float vr2 = -v[DD + d] * L2E;
        const float brz = -bb[DD + d] * L2E;
        __half* xh = Xhi + (size_t)b * DD + d;
        __half* xl = Xlo + (size_t)b * DD + d;
        const int odd = ch & 1;
        const int pr = ch >> 1;

        for (int k = 0; k < NCH; ++k) {
            __syncthreads();
            if (k == 0) continue;
            const int kk = k - 1, p = kk & 1;
            #pragma unroll
            for (int i = 0; i < CHUNK; ++i) {
                const int t = kk * CHUNK + i;
                const int s = t & (RING - 1);
                const float cc = sC[p][i][ch];
                const float rp = sRP[s][ch];
                const uint32_t hu = sXH[s][pr];
                const uint32_t lu = sXL[s][pr];
                const float2 hv = __half22float2(*(const __half2*)&hu);
                const float2 lv = __half22float2(*(const __half2*)&lu);
                const float xo = (odd ? hv.y : hv.x) + (odd ? lv.y : lv.x);
                const float zr = fmaf(vr2, cc, fmaf(rp, -L2E, brz));
                const float r  = rcpf(1.0f + ex2f(zr));
                const float h  = fmaf(r, cc - xo, xo);
                __half hh, hl;
                f16split(h, hh, hl);
                xh[(size_t)t * xs] = hh;
                xl[(size_t)t * xs] = hl;
            }
        }
        __syncthreads();
        {
            const int kk = NCH - 1, p = kk & 1;
            #pragma unroll
            for (int i = 0; i < CHUNK; ++i) {
                const int t = kk * CHUNK + i;
                const int s = t & (RING - 1);
                const float cc = sC[p][i][ch];
                const float rp = sRP[s][ch];
                const uint32_t hu = sXH[s][pr];
                const uint32_t lu = sXL[s][pr];
                const float2 hv = __half22float2(*(const __half2*)&hu);
                const float2 lv = __half22float2(*(const __half2*)&lu);
                const float xo = (odd ? hv.y : hv.x) + (odd ? lv.y : lv.x);
                const float zr = fmaf(vr2, cc, fmaf(rp, -L2E, brz));
                const float r  = rcpf(1.0f + ex2f(zr));
                const float h  = fmaf(r, cc - xo, xo);
                __half hh, hl;
                f16split(h, hh, hl);
                xh[(size_t)t * xs] = hh;
                xl[(size_t)t * xs] = hl;
            }
        }
        return;
    }
}

// ---------------------------------------------------------------- host side
extern "C" void kernel_launch(void* const* d_in, const int* in_sizes, int n_in,
                              void* d_out, int out_size) {
    const float* feats  = (const float*)d_in[0];
    const int*   slen   = (const int*)d_in[1];
    const float* conv_w = (const float*)d_in[2];
    const float* conv_b = (const float*)d_in[3];
    const float* sru_W  = (const float*)d_in[4];
    const float* sru_v  = (const float*)d_in[5];
    const float* sru_b  = (const float*)d_in[6];
    const float* fc_w   = (const float*)d_in[7];
    const float* fc_b   = (const float*)d_in[8];

    float* Up;
    __half *Xhi, *Xlo, *Wh;
    cudaGetSymbolAddress((void**)&Xhi, g_Xhi);
    cudaGetSymbolAddress((void**)&Xlo, g_Xlo);
    cudaGetSymbolAddress((void**)&Up,  g_U);
    cudaGetSymbolAddress((void**)&Wh,  g_Wh);

    cudaFuncSetAttribute(gemm_f16<0>,
                         cudaFuncAttributeMaxDynamicSharedMemorySize, SMEM_GEMM);
    cudaFuncSetAttribute(gemm_f16<1>,
                         cudaFuncAttributeMaxDynamicSharedMemorySize, SMEM_GEMM);

    // 0+1+4) fused prep
    {
        const int rem = out_size - LOGITS_ELEMS;
        float* outf = (float*)d_out + LOGITS_ELEMS;
        long long* outll = (long long*)((char*)d_out + (size_t)LOGITS_ELEMS * 4);
        prep_all<<<PREP_BLKS, 1024>>>(feats, conv_w, conv_b, Xhi, Xlo,
                                      sru_W, fc_w, Wh, slen, outf, outll, rem);
    }

    // 2) SRU layers
    for (int l = 0; l < LAY; ++l) {
        const size_t woff = (size_t)l * KTOT * NSRU;
        gemm_f16<0><<<dim3(NSRU / 128, MROWS / 128), 256, SMEM_GEMM>>>(
            Xhi, Wh + woff, Up, nullptr, NSRU);
        sru_rec<<<dim3(DD / 64, BB), 256>>>(Up, Xhi, Xlo,
                                            sru_v + (size_t)l * 2 * DD,
                                            sru_b + (size_t)l * 2 * DD);
    }

    // 3) FC (bias + (t,b)->(b,t) remap) into d_out
    {
        const size_t woff = (size_t)LAY * KTOT * NSRU;
        gemm_f16<1><<<dim3(NTOK / 128, MROWS / 128), 256, SMEM_GEMM>>>(
            Xhi, Wh + woff, (float*)d_out, fc_b, NTOK);
    }
}

// round 15
// speedup vs baseline: 2.1915x; 1.0821x over previous
#include <cuda_runtime.h>
#include <cuda_fp16.h>
#include <cstdint>

// ---------------------------------------------------------------- shapes
#define BB    8
#define CIN   16
#define FD    1024
#define TD    512
#define DD    1024
#define NTOK  512
#define LAY   4
#define MROWS (TD*BB)                 // 4096
#define LOGITS_ELEMS (BB*TD*NTOK)     // 2097152
#define KTOT  DD                      // 1024
#define NSRU  (3*DD)                  // 3072
#define WELEMS ((size_t)(LAY*NSRU + NTOK) * KTOT)

// ---------------------------------------------------------------- scratch
__device__ __half g_Xhi[(size_t)MROWS * DD];
__device__ __half g_Xlo[(size_t)MROWS * DD];
__device__ float  g_U  [(size_t)MROWS * NSRU];
__device__ __half g_Wh [WELEMS];
__device__ unsigned g_prog[32];          // per row-block GEMM progress

// ---------------------------------------------------------------- helpers
__device__ __forceinline__ uint32_t s2u(const void* p) {
    uint32_t a;
    asm("{ .reg .u64 t; cvta.to.shared.u64 t, %1; cvt.u32.u64 %0, t; }"
        : "=r"(a) : "l"(p));
    return a;
}
__device__ __forceinline__ void cpasync16(uint32_t dst, const void* src) {
    asm volatile("cp.async.cg.shared.global [%0], [%1], 16;"
                 :: "r"(dst), "l"(src) : "memory");
}
__device__ __forceinline__ void cpasync4(uint32_t dst, const void* src) {
    asm volatile("cp.async.ca.shared.global [%0], [%1], 4;"
                 :: "r"(dst), "l"(src) : "memory");
}
__device__ __forceinline__ void cp_commit() {
    asm volatile("cp.async.commit_group;" ::: "memory");
}
template <int N>
__device__ __forceinline__ void cp_wait() {
    asm volatile("cp.async.wait_group %0;" :: "n"(N) : "memory");
}
__device__ __forceinline__ void ldm_x4(uint32_t a[4], uint32_t addr) {
    asm volatile("ldmatrix.sync.aligned.m8n8.x4.shared.b16 {%0,%1,%2,%3}, [%4];"
                 : "=r"(a[0]), "=r"(a[1]), "=r"(a[2]), "=r"(a[3]) : "r"(addr));
}
__device__ __forceinline__ void ldm_x4t(uint32_t b[4], uint32_t addr) {
    asm volatile("ldmatrix.sync.aligned.m8n8.x4.trans.shared.b16 {%0,%1,%2,%3}, [%4];"
                 : "=r"(b[0]), "=r"(b[1]), "=r"(b[2]), "=r"(b[3]) : "r"(addr));
}
__device__ __forceinline__ void mma_f16(float c[4], const uint32_t a[4],
                                        const uint32_t b[2]) {
    asm volatile(
        "mma.sync.aligned.m16n8k16.row.col.f32.f16.f16.f32 "
        "{%0,%1,%2,%3}, {%4,%5,%6,%7}, {%8,%9}, {%0,%1,%2,%3};"
        : "+f"(c[0]), "+f"(c[1]), "+f"(c[2]), "+f"(c[3])
        : "r"(a[0]), "r"(a[1]), "r"(a[2]), "r"(a[3]), "r"(b[0]), "r"(b[1]));
}
__device__ __forceinline__ float ex2f(float x) {
    float r;
    asm("ex2.approx.f32 %0, %1;" : "=f"(r) : "f"(x));
    return r;
}
__device__ __forceinline__ float rcpf(float x) {
    float r;
    asm("rcp.approx.f32 %0, %1;" : "=f"(r) : "f"(x));
    return r;
}
__device__ __forceinline__ void f16split(float x, __half& hi, __half& lo) {
    hi = __float2half_rn(x);
    lo = __float2half_rn(x - __half2float(hi));
}
__device__ __forceinline__ unsigned ldcg_u32(const unsigned* p) {
    unsigned v;
    asm volatile("ld.global.cg.u32 %0, [%1];" : "=r"(v) : "l"(p));
    return v;
}

// smem per stage (fp16, BK=64): A 128x(64+8)h = 18432B, B 64x(128+8)h = 17408B.
#define BK      64
#define A_PADB  144
#define B_PADB  272
#define BOFF    18432
#define STAGE_B 35840
#define NSTAGES 3
#define SMEM_GEMM (NSTAGES * STAGE_B)   // 107520 (sru slice fits inside)
#define NKITER (KTOT / BK)              // 16

// sru constants
#define CHUNK 8
#define RING  32
#define NCH   (TD / CHUNK)   // 64
#define GEMM_BLKS (24 * 32)  // 768
#define SRU_BLKS  128

// ---------------------------------------------------------------- GEMM load
__device__ __forceinline__ void load_stage(uint32_t st_base,
                                           const __half* __restrict__ Ah,
                                           const __half* __restrict__ Wh,
                                           int rowBase, int colBase, int kt,
                                           int Nglob, int tid) {
    #pragma unroll
    for (int i = 0; i < 4; ++i) {
        const int q = tid + i * 256;
        const int ar = q >> 3, ac = q & 7;
        cpasync16(st_base + ar * A_PADB + ac * 16,
                  Ah + (size_t)(rowBase + ar) * KTOT + kt + ac * 8);
        const int br = q >> 4, bc = q & 15;
        cpasync16(st_base + BOFF + br * B_PADB + bc * 16,
                  Wh + (size_t)(kt + br) * Nglob + colBase + bc * 8);
    }
    cp_commit();
}

// ---------------------------------------------------------------- fused GEMM+SRU
// Blocks 0..767: GEMM layer tile (epilogue bumps g_prog[rowBlk]).
// Blocks 768..895: warp-specialized SRU gated on g_prog.
__global__ void __launch_bounds__(256, 2)
gemm_sru(const __half* __restrict__ Ah,
         const __half* __restrict__ Wh,
         float* __restrict__ U,
         __half* __restrict__ Xhi, __half* __restrict__ Xlo,
         const float* __restrict__ v, const float* __restrict__ bb,
         unsigned target) {
    extern __shared__ __align__(16) char smem_raw[];
    const int tid = threadIdx.x;
    const float L2E = 1.4426950408889634f;
    const size_t us = (size_t)BB * 3 * DD;
    const size_t xs = (size_t)BB * DD;

    if (blockIdx.x < GEMM_BLKS) {
        // ===================== GEMM =====================
        const uint32_t sb = s2u(smem_raw);
        const int wid = tid >> 5, lane = tid & 31;
        const int wm = wid & 3, wn = wid >> 2;
        const int bx = blockIdx.x % 24, by = blockIdx.x / 24;
        const int rowBase = by * 128;
        const int colBase = bx * 128;

        float acc[2][8][4];
        #pragma unroll
        for (int i = 0; i < 2; ++i)
            #pragma unroll
            for (int j = 0; j < 8; ++j)
                #pragma unroll
                for (int k = 0; k < 4; ++k) acc[i][j][k] = 0.0f;

        load_stage(sb,           Ah, Wh, rowBase, colBase, 0,  NSRU, tid);
        load_stage(sb + STAGE_B, Ah, Wh, rowBase, colBase, BK, NSRU, tid);

        const int lr  = lane & 15;
        const int lc  = lane >> 4;
        const int bng = lane >> 4;

        int st = 0;
        for (int k = 0; k < NKITER; ++k) {
            if (k + 2 <= NKITER) cp_wait<1>(); else cp_wait<0>();
            __syncthreads();
            if (k + 2 < NKITER)
                load_stage(sb + ((st + 2) % 3) * STAGE_B, Ah, Wh,
                           rowBase, colBase, (k + 2) * BK, NSRU, tid);

            const uint32_t abase = sb + st * STAGE_B;
            const uint32_t bbase = abase + BOFF;

            #pragma unroll
            for (int kk = 0; kk < 4; ++kk) {
                const int arow0 = wm * 32 + lr;
                const int acolB = (kk * 16 + lc * 8) * 2;
                uint32_t a0[2][4], bfr[4][4];
                #pragma unroll
                for (int mt = 0; mt < 2; ++mt)
                    ldm_x4(a0[mt], abase + (arow0 + mt * 16) * A_PADB + acolB);
                const uint32_t brow = bbase + (kk * 16 + lr) * B_PADB;
                #pragma unroll
                for (int np = 0; np < 4; ++np)
                    ldm_x4t(bfr[np], brow + (wn * 64 + np * 16 + bng * 8) * 2);
                #pragma unroll
                for (int mt = 0; mt < 2; ++mt)
                    #pragma unroll
                    for (int np = 0; np < 4; ++np) {
                        mma_f16(acc[mt][2 * np + 0], a0[mt], &bfr[np][0]);
                        mma_f16(acc[mt][2 * np + 1], a0[mt], &bfr[np][2]);
                    }
            }
            st = (st + 1) % 3;
        }

        const int rq = lane >> 2;
        const int cq = (lane & 3) * 2;
        #pragma unroll
        for (int mt = 0; mt < 2; ++mt) {
            #pragma unroll
            for (int half = 0; half < 2; ++half) {
                const int m = rowBase + wm * 32 + mt * 16 + half * 8 + rq;
                float* crow = U + (size_t)m * NSRU + colBase + wn * 64;
                #pragma unroll
                for (int nt = 0; nt < 8; ++nt) {
                    float2 vv;
                    vv.x = acc[mt][nt][half * 2 + 0];
                    vv.y = acc[mt][nt][half * 2 + 1];
                    *(float2*)(crow + nt * 8 + cq) = vv;
                }
            }
        }
        __threadfence();
        __syncthreads();
        if (tid == 0) atomicAdd(&g_prog[by], 1u);
        return;
    }

    // ===================== SRU =====================
    const int sblk = blockIdx.x - GEMM_BLKS;
    const int dbase = (sblk & 15) * 64;
    const int b = sblk >> 4;
    const int wid = tid >> 5;

    // smem slices inside the dynamic buffer
    const uint32_t sbase = s2u(smem_raw);
    const uint32_t aXT = sbase;                 // [RING][64] f32
    const uint32_t aFP = sbase + 8192;
    const uint32_t aRP = sbase + 16384;
    const uint32_t aXH = sbase + 24576;         // [RING][32] u32
    const uint32_t aXL = sbase + 28672;
    const uint32_t aC  = sbase + 32768;         // [2][CHUNK][64] f32
    float*    fXT = (float*)smem_raw;
    float*    fFP = (float*)(smem_raw + 8192);
    float*    fRP = (float*)(smem_raw + 16384);
    uint32_t* uXH = (uint32_t*)(smem_raw + 24576);
    uint32_t* uXL = (uint32_t*)(smem_raw + 28672);
    float*    fC  = (float*)(smem_raw + 32768);

    if (wid >= 4) {
        // ---------- loader warps (tid 128..255), gated on g_prog ----------
        const int j = tid - 128;
        const float* ubase = U + (size_t)b * 3 * DD + dbase;
        const __half* xbase_h = Xhi + (size_t)b * DD + dbase;
        const __half* xbase_l = Xlo + (size_t)b * DD + dbase;

        const void* src0;  uint32_t dst0;
        const void* src1;  uint32_t dst1;
        {
            #pragma unroll
            for (int e = 0; e < 2; ++e) {
                const int q = 2 * j + e;
                const void* s;
                uint32_t dd;
                if (q < 64)       { s = ubase + q;                  dd = aXT + q * 4; }
                else if (q < 128) { s = ubase + DD + (q - 64);      dd = aFP + (q - 64) * 4; }
                else if (q < 192) { s = ubase + 2 * DD + (q - 128); dd = aRP + (q - 128) * 4; }
                else {
                    const int qp = q - 192;
                    const int pr = qp >> 1;
                    if ((qp & 1) == 0) { s = xbase_h + 2 * pr; dd = aXH + pr * 4; }
                    else               { s = xbase_l + 2 * pr; dd = aXL + pr * 4; }
                }
                if (e == 0) { src0 = s; dst0 = dd; } else { src1 = s; dst1 = dd; }
            }
        }
        const bool p0 = (2 * j)     >= 192;
        const bool p1 = (2 * j + 1) >= 192;
        const int q0 = 2 * j, q1 = 2 * j + 1;

        // gate helper: chunk jj needs row-block jj>>1 fully produced
        #define GATE(jj) do { \
            if (tid == 128) { \
                const unsigned* cp = &g_prog[(jj) >> 1]; \
                while (ldcg_u32(cp) < target) __nanosleep(64); \
            } \
            asm volatile("bar.sync 1, 128;" ::: "memory"); \
        } while (0)

        // prologue: chunks 0,1
        for (int ch = 0; ch < 2; ++ch) {
            GATE(ch);
            #pragma unroll 1
            for (int i = 0; i < CHUNK; ++i) {
                const int t = ch * CHUNK + i;
                const int s = t & (RING - 1);
                cpasync4(dst0 + s * (q0 < 192 ? 256 : 128),
                         p0 ? (const void*)((const __half*)src0 + (size_t)t * xs)
                            : (const void*)((const float*)src0 + (size_t)t * us));
                cpasync4(dst1 + s * (q1 < 192 ? 256 : 128),
                         p1 ? (const void*)((const __half*)src1 + (size_t)t * xs)
                            : (const void*)((const float*)src1 + (size_t)t * us));
                cp_commit();
            }
        }
        cp_wait<CHUNK>();

        for (int k = 0; k < NCH; ++k) {
            __syncthreads();
            if (k + 2 < NCH) {
                GATE(k + 2);
                #pragma unroll 1
                for (int i = 0; i < CHUNK; ++i) {
                    const int t = (k + 2) * CHUNK + i;
                    const int s = t & (RING - 1);
                    cpasync4(dst0 + s * (q0 < 192 ? 256 : 128),
                             p0 ? (const void*)((const __half*)src0 + (size_t)t * xs)
                                : (const void*)((const float*)src0 + (size_t)t * us));
                    cpasync4(dst1 + s * (q1 < 192 ? 256 : 128),
                             p1 ? (const void*)((const __half*)src1 + (size_t)t * xs)
                                : (const void*)((const float*)src1 + (size_t)t * us));
                    cp_commit();
                }
                cp_wait<CHUNK>();
            } else {
                cp_wait<0>();
            }
        }
        __syncthreads();
        #undef GATE
    } else if (wid < 2) {
        // ---------- c-chain warps ----------
        const int ch = tid;
        const int d = dbase + ch;
        const float vf2 = -v[d] * L2E;
        const float bfz = -bb[d] * L2E;

        float c = 0.0f;
        for (int k = 0; k < NCH; ++k) {
            __syncthreads();
            const int t0 = k * CHUNK;
            float xt_c = fXT[(t0 & (RING - 1)) * 64 + ch];
            float wf_c = fmaf(fFP[(t0 & (RING - 1)) * 64 + ch], -L2E, bfz);
            #pragma unroll
            for (int i = 0; i < CHUNK; ++i) {
                float xt_n = 0.0f, wf_n = 0.0f;
                if (i + 1 < CHUNK) {
                    const int s1 = (t0 + i + 1) & (RING - 1);
                    xt_n = fXT[s1 * 64 + ch];
                    wf_n = fmaf(fFP[s1 * 64 + ch], -L2E, bfz);
                }
                const float zf = fmaf(vf2, c, wf_c);
                const float f  = rcpf(1.0f + ex2f(zf));
                c = fmaf(f, c - xt_c, xt_c);
                fC[((k & 1) * CHUNK + i) * 64 + ch] = c;
                xt_c = xt_n;  wf_c = wf_n;
            }
        }
        __syncthreads();
    } else {
        // ---------- r/readout warps (lag one chunk) ----------
        const int ch = tid - 64;
        const int d = dbase + ch;
        const float vr2 = -v[DD + d] * L2E;
        const float brz = -bb[DD + d] * L2E;
        __half* xh = Xhi + (size_t)b * DD + d;
        __half* xl = Xlo + (size_t)b * DD + d;
        const int odd = ch & 1;
        const int pr = ch >> 1;

        for (int k = 0; k < NCH; ++k) {
            __syncthreads();
            if (k == 0) continue;
            const int kk = k - 1, p = kk & 1;
            #pragma unroll
            for (int i = 0; i < CHUNK; ++i) {
                const int t = kk * CHUNK + i;
                const int s = t & (RING - 1);
                const float cc = fC[(p * CHUNK + i) * 64 + ch];
                const float rp = fRP[s * 64 + ch];
                const uint32_t hu = uXH[s * 32 + pr];
                const uint32_t lu = uXL[s * 32 + pr];
                const float2 hv = __half22float2(*(const __half2*)&hu);
                const float2 lv = __half22float2(*(const __half2*)&lu);
                const float xo = (odd ? hv.y : hv.x) + (odd ? lv.y : lv.x);
                const float zr = fmaf(vr2, cc, fmaf(rp, -L2E, brz));
                const float r  = rcpf(1.0f + ex2f(zr));
                const float h  = fmaf(r, cc - xo, xo);
                __half hh, hl;
                f16split(h, hh, hl);
                xh[(size_t)t * xs] = hh;
                xl[(size_t)t * xs] = hl;
            }
        }
        __syncthreads();
        {
            const int kk = NCH - 1, p = kk & 1;
            #pragma unroll
            for (int i = 0; i < CHUNK; ++i) {
                const int t = kk * CHUNK + i;
                const int s = t & (RING - 1);
                const float cc = fC[(p * CHUNK + i) * 64 + ch];
                const float rp = fRP[s * 64 + ch];
                const uint32_t hu = uXH[s * 32 + pr];
                const uint32_t lu = uXL[s * 32 + pr];
                const float2 hv = __half22float2(*(const __half2*)&hu);
                const float2 lv = __half22float2(*(const __half2*)&lu);
                const float xo = (odd ? hv.y : hv.x) + (odd ? lv.y : lv.x);
                const float zr = fmaf(vr2, cc, fmaf(rp, -L2E, brz));
                const float r  = rcpf(1.0f + ex2f(zr));
                const float h  = fmaf(r, cc - xo, xo);
                __half hh, hl;
                f16split(h, hh, hl);
                xh[(size_t)t * xs] = hh;
                xl[(size_t)t * xs] = hl;
            }
        }
    }
}

// ---------------------------------------------------------------- FC GEMM
__global__ void __launch_bounds__(256, 2)
gemm_fc(const __half* __restrict__ Ah, const __half* __restrict__ Wh,
        float* __restrict__ C, const float* __restrict__ bias) {
    extern __shared__ __align__(16) char smem_raw[];
    const uint32_t sb = s2u(smem_raw);

    const int tid = threadIdx.x;
    const int wid = tid >> 5, lane = tid & 31;
    const int wm = wid & 3, wn = wid >> 2;
    const int rowBase = blockIdx.y * 128;
    const int colBase = blockIdx.x * 128;

    float acc[2][8][4];
    #pragma unroll
    for (int i = 0; i < 2; ++i)
        #pragma unroll
        for (int j = 0; j < 8; ++j)
            #pragma unroll
            for (int k = 0; k < 4; ++k) acc[i][j][k] = 0.0f;

    load_stage(sb,           Ah, Wh, rowBase, colBase, 0,  NTOK, tid);
    load_stage(sb + STAGE_B, Ah, Wh, rowBase, colBase, BK, NTOK, tid);

    const int lr  = lane & 15;
    const int lc  = lane >> 4;
    const int bng = lane >> 4;

    int st = 0;
    for (int k = 0; k < NKITER; ++k) {
        if (k + 2 <= NKITER) cp_wait<1>(); else cp_wait<0>();
        __syncthreads();
        if (k + 2 < NKITER)
            load_stage(sb + ((st + 2) % 3) * STAGE_B, Ah, Wh,
                       rowBase, colBase, (k + 2) * BK, NTOK, tid);

        const uint32_t abase = sb + st * STAGE_B;
        const uint32_t bbase = abase + BOFF;

        #pragma unroll
        for (int kk = 0; kk < 4; ++kk) {
            const int arow0 = wm * 32 + lr;
            const int acolB = (kk * 16 + lc * 8) * 2;
            uint32_t a0[2][4], bfr[4][4];
            #pragma unroll
            for (int mt = 0; mt < 2; ++mt)
                ldm_x4(a0[mt], abase + (arow0 + mt * 16) * A_PADB + acolB);
            const uint32_t brow = bbase + (kk * 16 + lr) * B_PADB;
            #pragma unroll
            for (int np = 0; np < 4; ++np)
                ldm_x4t(bfr[np], brow + (wn * 64 + np * 16 + bng * 8) * 2);
            #pragma unroll
            for (int mt = 0; mt < 2; ++mt)
                #pragma unroll
                for (int np = 0; np < 4; ++np) {
                    mma_f16(acc[mt][2 * np + 0], a0[mt], &bfr[np][0]);
                    mma_f16(acc[mt][2 * np + 1], a0[mt], &bfr[np][2]);
                }
        }
        st = (st + 1) % 3;
    }

    const int rq = lane >> 2;
    const int cq = (lane & 3) * 2;
    #pragma unroll
    for (int mt = 0; mt < 2; ++mt) {
        #pragma unroll
        for (int half = 0; half < 2; ++half) {
            const int m = rowBase + wm * 32 + mt * 16 + half * 8 + rq;
            const int orow = (m & (BB - 1)) * TD + (m >> 3);
            float* crow = C + (size_t)orow * NTOK + colBase + wn * 64;
            #pragma unroll
            for (int nt = 0; nt < 8; ++nt) {
                float2 vv;
                vv.x = acc[mt][nt][half * 2 + 0] +
                       bias[colBase + wn * 64 + nt * 8 + cq + 0];
                vv.y = acc[mt][nt][half * 2 + 1] +
                       bias[colBase + wn * 64 + nt * 8 + cq + 1];
                *(float2*)(crow + nt * 8 + cq) = vv;
            }
        }
    }
}

// ---------------------------------------------------------------- fused prep
#define CONV_BLKS  4096
#define SPLIT_BLKS 3200
#define PREP_BLKS  (CONV_BLKS + SPLIT_BLKS + 1)

__global__ void __launch_bounds__(1024)
prep_all(const float* __restrict__ feats, const float* __restrict__ w,
         const float* __restrict__ bptr,
         __half* __restrict__ Xhi, __half* __restrict__ Xlo,
         const float* __restrict__ Wsru, const float* __restrict__ Wfc,
         __half* __restrict__ Wh,
         const int* __restrict__ lenbuf, float* outf, long long* outll,
         int rem) {
    __shared__ float s[32][33];
    const int blk = blockIdx.x;
    const int tid = threadIdx.x;

    if (blk < CONV_BLKS) {
        const int tx = tid & 31, ty = tid >> 5;
        const int bx = blk & 15, by = (blk >> 4) & 31, bz = blk >> 9;
        const int t = bx * 32 + tx;
        const int f = by * 32 + ty;
        const int b = bz;

        float acc = bptr[0];
        const float* base = feats + ((size_t)(b * CIN) * FD + f) * TD + t;
        #pragma unroll
        for (int c = 0; c < CIN; ++c)
            acc = fmaf(base[(size_t)c * FD * TD], w[c], acc);
        s[ty][tx] = fmaxf(acc, 0.0f);
        __syncthreads();

        const int t2 = bx * 32 + ty;
        const int f2 = by * 32 + tx;
        const float x = s[tx][ty];
        const size_t o = (size_t)(t2 * BB + b) * DD + f2;
        __half h, l;
        f16split(x, h, l);
        Xhi[o] = h;  Xlo[o] = l;
    } else if (blk < CONV_BLKS + SPLIT_BLKS) {
        const size_t i = (size_t)(blk - CONV_BLKS) * 1024 + tid;
        const size_t n4sru = (size_t)LAY * NSRU * KTOT / 4;
        const float4 x = (i < n4sru) ? ((const float4*)Wsru)[i]
                                     : ((const float4*)Wfc)[i - n4sru];
        __half h[4];
        h[0] = __float2half_rn(x.x);
        h[1] = __float2half_rn(x.y);
        h[2] = __float2half_rn(x.z);
        h[3] = __float2half_rn(x.w);
        ((ulonglong1*)Wh)[i] = *(ulonglong1*)h;
    } else {
        if (tid < 32) g_prog[tid] = 0u;        // reset progress counters
        if (tid < BB && rem > 0) {
            const bool in64 = (lenbuf[1] == 0 && lenbuf[3] == 0 &&
                               lenbuf[5] == 0 && lenbuf[7] == 0);
            const long long val = in64 ? (long long)lenbuf[2 * tid]
                                       : (long long)lenbuf[tid];
            const long long hv = val >> 1;
            if (rem >= 16)      outll[tid] = hv;
            else if (rem >= 8)  outf[tid]  = (float)hv;
        }
    }
}

// ---------------------------------------------------------------- host side
extern "C" void kernel_launch(void* const* d_in, const int* in_sizes, int n_in,
                              void* d_out, int out_size) {
    const float* feats  = (const float*)d_in[0];
    const int*   slen   = (const int*)d_in[1];
    const float* conv_w = (const float*)d_in[2];
    const float* conv_b = (const float*)d_in[3];
    const float* sru_W  = (const float*)d_in[4];
    const float* sru_v  = (const float*)d_in[5];
    const float* sru_b  = (const float*)d_in[6];
    const float* fc_w   = (const float*)d_in[7];
    const float* fc_b   = (const float*)d_in[8];

    float* Up;
    __half *Xhi, *Xlo, *Wh;
    cudaGetSymbolAddress((void**)&Xhi, g_Xhi);
    cudaGetSymbolAddress((void**)&Xlo, g_Xlo);
    cudaGetSymbolAddress((void**)&Up,  g_U);
    cudaGetSymbolAddress((void**)&Wh,  g_Wh);

    cudaFuncSetAttribute(gemm_sru,
                         cudaFuncAttributeMaxDynamicSharedMemorySize, SMEM_GEMM);
    cudaFuncSetAttribute(gemm_fc,
                         cudaFuncAttributeMaxDynamicSharedMemorySize, SMEM_GEMM);

    // prep: conv + weight split + lengths tail + counter reset
    {
        const int rem = out_size - LOGITS_ELEMS;
        float* outf = (float*)d_out + LOGITS_ELEMS;
        long long* outll = (long long*)((char*)d_out + (size_t)LOGITS_ELEMS * 4);
        prep_all<<<PREP_BLKS, 1024>>>(feats, conv_w, conv_b, Xhi, Xlo,
                                      sru_W, fc_w, Wh, slen, outf, outll, rem);
    }

    // SRU layers: fused GEMM + recurrence, overlapped via g_prog gating
    for (int l = 0; l < LAY; ++l) {
        const size_t woff = (size_t)l * KTOT * NSRU;
        gemm_sru<<<GEMM_BLKS + SRU_BLKS, 256, SMEM_GEMM>>>(
            Xhi, Wh + woff, Up, Xhi, Xlo,
            sru_v + (size_t)l * 2 * DD, sru_b + (size_t)l * 2 * DD,
            24u * (unsigned)(l + 1));
    }

    // FC (bias + (t,b)->(b,t) remap) into d_out
    {
        const size_t woff = (size_t)LAY * KTOT * NSRU;
        gemm_fc<<<dim3(NTOK / 128, MROWS / 128), 256, SMEM_GEMM>>>(
            Xhi, Wh + woff, (float*)d_out, fc_b);
    }
}

// round 16
// speedup vs baseline: 2.2067x; 1.0069x over previous
#include <cuda_runtime.h>
#include <cuda_fp16.h>
#include <cstdint>

// ---------------------------------------------------------------- shapes
#define BB    8
#define CIN   16
#define FD    1024
#define TD    512
#define DD    1024
#define NTOK  512
#define LAY   4
#define MROWS (TD*BB)                 // 4096
#define LOGITS_ELEMS (BB*TD*NTOK)     // 2097152
#define KTOT  DD                      // 1024
#define NSRU  (3*DD)                  // 3072
#define WELEMS ((size_t)(LAY*NSRU + NTOK) * KTOT)

// ---------------------------------------------------------------- scratch
__device__ __half g_Xhi[(size_t)MROWS * DD];
__device__ __half g_Xlo[(size_t)MROWS * DD];
__device__ float  g_U  [(size_t)MROWS * NSRU];
__device__ __half g_Wh [WELEMS];
__device__ unsigned g_prog[32];    // GEMM col-tiles done per row-block (cumulative)
__device__ unsigned g_sprog[32];   // sru blocks done per row-block (cumulative)
__device__ unsigned g_task;        // work-queue head

// ---------------------------------------------------------------- helpers
__device__ __forceinline__ uint32_t s2u(const void* p) {
    uint32_t a;
    asm("{ .reg .u64 t; cvta.to.shared.u64 t, %1; cvt.u32.u64 %0, t; }"
        : "=r"(a) : "l"(p));
    return a;
}
__device__ __forceinline__ void cpasync16(uint32_t dst, const void* src) {
    asm volatile("cp.async.cg.shared.global [%0], [%1], 16;"
                 :: "r"(dst), "l"(src) : "memory");
}
__device__ __forceinline__ void cpasync4(uint32_t dst, const void* src) {
    asm volatile("cp.async.ca.shared.global [%0], [%1], 4;"
                 :: "r"(dst), "l"(src) : "memory");
}
__device__ __forceinline__ void cp_commit() {
    asm volatile("cp.async.commit_group;" ::: "memory");
}
template <int N>
__device__ __forceinline__ void cp_wait() {
    asm volatile("cp.async.wait_group %0;" :: "n"(N) : "memory");
}
__device__ __forceinline__ void ldm_x4(uint32_t a[4], uint32_t addr) {
    asm volatile("ldmatrix.sync.aligned.m8n8.x4.shared.b16 {%0,%1,%2,%3}, [%4];"
                 : "=r"(a[0]), "=r"(a[1]), "=r"(a[2]), "=r"(a[3]) : "r"(addr));
}
__device__ __forceinline__ void ldm_x4t(uint32_t b[4], uint32_t addr) {
    asm volatile("ldmatrix.sync.aligned.m8n8.x4.trans.shared.b16 {%0,%1,%2,%3}, [%4];"
                 : "=r"(b[0]), "=r"(b[1]), "=r"(b[2]), "=r"(b[3]) : "r"(addr));
}
__device__ __forceinline__ void mma_f16(float c[4], const uint32_t a[4],
                                        const uint32_t b[2]) {
    asm volatile(
        "mma.sync.aligned.m16n8k16.row.col.f32.f16.f16.f32 "
        "{%0,%1,%2,%3}, {%4,%5,%6,%7}, {%8,%9}, {%0,%1,%2,%3};"
        : "+f"(c[0]), "+f"(c[1]), "+f"(c[2]), "+f"(c[3])
        : "r"(a[0]), "r"(a[1]), "r"(a[2]), "r"(a[3]), "r"(b[0]), "r"(b[1]));
}
__device__ __forceinline__ float ex2f(float x) {
    float r;
    asm("ex2.approx.f32 %0, %1;" : "=f"(r) : "f"(x));
    return r;
}
__device__ __forceinline__ float rcpf(float x) {
    float r;
    asm("rcp.approx.f32 %0, %1;" : "=f"(r) : "f"(x));
    return r;
}
__device__ __forceinline__ void f16split(float x, __half& hi, __half& lo) {
    hi = __float2half_rn(x);
    lo = __float2half_rn(x - __half2float(hi));
}
__device__ __forceinline__ unsigned ldcg_u32(const unsigned* p) {
    unsigned v;
    asm volatile("ld.global.cg.u32 %0, [%1];" : "=r"(v) : "l"(p));
    return v;
}

// smem per stage (fp16, BK=64): A 128x(64+8)h = 18432B, B 64x(128+8)h = 17408B.
#define BK      64
#define A_PADB  144
#define B_PADB  272
#define BOFF    18432
#define STAGE_B 35840
#define NSTAGES 3
#define SMEM_GEMM (NSTAGES * STAGE_B)   // 107520
#define NKITER (KTOT / BK)              // 16

// sru constants
#define CHUNK 8
#define RING  32
#define NCH   (TD / CHUNK)   // 64

// task queue
#define TASKS_PER_LAYER 896      // 768 GEMM + 128 sru
#define NTASKS (LAY * TASKS_PER_LAYER + 128)   // + FC tiles = 3712
#define MEGA_GRID 296

// ---------------------------------------------------------------- GEMM load
__device__ __forceinline__ void load_stage(uint32_t st_base,
                                           const __half* __restrict__ Ah,
                                           const __half* __restrict__ Wh,
                                           int rowBase, int colBase, int kt,
                                           int Nglob, int tid) {
    #pragma unroll
    for (int i = 0; i < 4; ++i) {
        const int q = tid + i * 256;
        const int ar = q >> 3, ac = q & 7;
        cpasync16(st_base + ar * A_PADB + ac * 16,
                  Ah + (size_t)(rowBase + ar) * KTOT + kt + ac * 8);
        const int br = q >> 4, bc = q & 15;
        cpasync16(st_base + BOFF + br * B_PADB + bc * 16,
                  Wh + (size_t)(kt + br) * Nglob + colBase + bc * 8);
    }
    cp_commit();
}

// ---------------------------------------------------------------- GEMM tile task
__device__ void gemm_tile(const __half* __restrict__ Ah,
                          const __half* __restrict__ Wg,
                          float* __restrict__ Cout,
                          const float* __restrict__ bias,
                          int Nglob, int rowBase, int colBase,
                          bool fcmode, char* smem_raw, unsigned sgate) {
    const uint32_t sb = s2u(smem_raw);
    const int tid = threadIdx.x;

    if (sgate) {   // wait until previous layer's sru finished rows of this block
        if (tid == 0) {
            const unsigned* cp = &g_sprog[rowBase >> 7];
            while (ldcg_u32(cp) < sgate) __nanosleep(64);
        }
        __syncthreads();
        __threadfence();
    }

    const int wid = tid >> 5, lane = tid & 31;
    const int wm = wid & 3, wn = wid >> 2;

    float acc[2][8][4];
    #pragma unroll
    for (int i = 0; i < 2; ++i)
        #pragma unroll
        for (int j = 0; j < 8; ++j)
            #pragma unroll
            for (int k = 0; k < 4; ++k) acc[i][j][k] = 0.0f;

    load_stage(sb,           Ah, Wg, rowBase, colBase, 0,  Nglob, tid);
    load_stage(sb + STAGE_B, Ah, Wg, rowBase, colBase, BK, Nglob, tid);

    const int lr  = lane & 15;
    const int lc  = lane >> 4;
    const int bng = lane >> 4;

    int st = 0;
    for (int k = 0; k < NKITER; ++k) {
        if (k + 2 <= NKITER) cp_wait<1>(); else cp_wait<0>();
        __syncthreads();
        if (k + 2 < NKITER)
            load_stage(sb + ((st + 2) % 3) * STAGE_B, Ah, Wg,
                       rowBase, colBase, (k + 2) * BK, Nglob, tid);

        const uint32_t abase = sb + st * STAGE_B;
        const uint32_t bbase = abase + BOFF;

        #pragma unroll
        for (int kk = 0; kk < 4; ++kk) {
            const int arow0 = wm * 32 + lr;
            const int acolB = (kk * 16 + lc * 8) * 2;
            uint32_t a0[2][4], bfr[4][4];
            #pragma unroll
            for (int mt = 0; mt < 2; ++mt)
                ldm_x4(a0[mt], abase + (arow0 + mt * 16) * A_PADB + acolB);
            const uint32_t brow = bbase + (kk * 16 + lr) * B_PADB;
            #pragma unroll
            for (int np = 0; np < 4; ++np)
                ldm_x4t(bfr[np], brow + (wn * 64 + np * 16 + bng * 8) * 2);
            #pragma unroll
            for (int mt = 0; mt < 2; ++mt)
                #pragma unroll
                for (int np = 0; np < 4; ++np) {
                    mma_f16(acc[mt][2 * np + 0], a0[mt], &bfr[np][0]);
                    mma_f16(acc[mt][2 * np + 1], a0[mt], &bfr[np][2]);
                }
        }
        st = (st + 1) % 3;
    }

    const int rq = lane >> 2;
    const int cq = (lane & 3) * 2;
    #pragma unroll
    for (int mt = 0; mt < 2; ++mt) {
        #pragma unroll
        for (int half = 0; half < 2; ++half) {
            const int m = rowBase + wm * 32 + mt * 16 + half * 8 + rq;
            const int orow = fcmode ? ((m & (BB - 1)) * TD + (m >> 3)) : m;
            float* crow = Cout + (size_t)orow * Nglob + colBase + wn * 64;
            #pragma unroll
            for (int nt = 0; nt < 8; ++nt) {
                float2 vv;
                vv.x = acc[mt][nt][half * 2 + 0];
                vv.y = acc[mt][nt][half * 2 + 1];
                if (fcmode) {
                    vv.x += bias[colBase + wn * 64 + nt * 8 + cq + 0];
                    vv.y += bias[colBase + wn * 64 + nt * 8 + cq + 1];
                }
                *(float2*)(crow + nt * 8 + cq) = vv;
            }
        }
    }
    if (!fcmode) {
        __threadfence();
        __syncthreads();
        if (tid == 0) atomicAdd(&g_prog[rowBase >> 7], 1u);
    }
}

// ---------------------------------------------------------------- SRU task
__device__ void sru_task(const float* __restrict__ U,
                         __half* __restrict__ Xhi, __half* __restrict__ Xlo,
                         const float* __restrict__ v, const float* __restrict__ bb,
                         int sblk, unsigned ptarget, char* smem_raw) {
    const int tid = threadIdx.x;
    const int wid = tid >> 5;
    const int dbase = (sblk & 15) * 64;
    const int b = sblk >> 4;
    const size_t us = (size_t)BB * 3 * DD;
    const size_t xs = (size_t)BB * DD;
    const float L2E = 1.4426950408889634f;

    const uint32_t sbase = s2u(smem_raw);
    const uint32_t aXT = sbase;
    const uint32_t aFP = sbase + 8192;
    const uint32_t aRP = sbase + 16384;
    const uint32_t aXH = sbase + 24576;
    const uint32_t aXL = sbase + 28672;
    float*    fXT = (float*)smem_raw;
    float*    fFP = (float*)(smem_raw + 8192);
    float*    fRP = (float*)(smem_raw + 16384);
    uint32_t* uXH = (uint32_t*)(smem_raw + 24576);
    uint32_t* uXL = (uint32_t*)(smem_raw + 28672);
    float*    fC  = (float*)(smem_raw + 32768);

    if (wid >= 4) {
        // ---------- loader warps, gated on g_prog ----------
        const int j = tid - 128;
        const float* ubase = U + (size_t)b * 3 * DD + dbase;
        const __half* xbase_h = Xhi + (size_t)b * DD + dbase;
        const __half* xbase_l = Xlo + (size_t)b * DD + dbase;

        const void* src0;  uint32_t dst0;
        const void* src1;  uint32_t dst1;
        {
            #pragma unroll
            for (int e = 0; e < 2; ++e) {
                const int q = 2 * j + e;
                const void* s;
                uint32_t dd;
                if (q < 64)       { s = ubase + q;                  dd = aXT + q * 4; }
                else if (q < 128) { s = ubase + DD + (q - 64);      dd = aFP + (q - 64) * 4; }
                else if (q < 192) { s = ubase + 2 * DD + (q - 128); dd = aRP + (q - 128) * 4; }
                else {
                    const int qp = q - 192;
                    const int pr = qp >> 1;
                    if ((qp & 1) == 0) { s = xbase_h + 2 * pr; dd = aXH + pr * 4; }
                    else               { s = xbase_l + 2 * pr; dd = aXL + pr * 4; }
                }
                if (e == 0) { src0 = s; dst0 = dd; } else { src1 = s; dst1 = dd; }
            }
        }
        const bool p0 = (2 * j)     >= 192;
        const bool p1 = (2 * j + 1) >= 192;
        const int q0 = 2 * j, q1 = 2 * j + 1;

        #define GATE(jj) do { \
            if (tid == 128) { \
                const unsigned* cp = &g_prog[(jj) >> 1]; \
                while (ldcg_u32(cp) < ptarget) __nanosleep(64); \
            } \
            asm volatile("bar.sync 1, 128;" ::: "memory"); \
        } while (0)

        for (int ch = 0; ch < 2; ++ch) {
            GATE(ch);
            #pragma unroll 1
            for (int i = 0; i < CHUNK; ++i) {
                const int t = ch * CHUNK + i;
                const int s = t & (RING - 1);
                cpasync4(dst0 + s * (q0 < 192 ? 256 : 128),
                         p0 ? (const void*)((const __half*)src0 + (size_t)t * xs)
                            : (const void*)((const float*)src0 + (size_t)t * us));
                cpasync4(dst1 + s * (q1 < 192 ? 256 : 128),
                         p1 ? (const void*)((const __half*)src1 + (size_t)t * xs)
                            : (const void*)((const float*)src1 + (size_t)t * us));
                cp_commit();
            }
        }
        cp_wait<CHUNK>();

        for (int k = 0; k < NCH; ++k) {
            __syncthreads();
            if (k + 2 < NCH) {
                GATE(k + 2);
                #pragma unroll 1
                for (int i = 0; i < CHUNK; ++i) {
                    const int t = (k + 2) * CHUNK + i;
                    const int s = t & (RING - 1);
                    cpasync4(dst0 + s * (q0 < 192 ? 256 : 128),
                             p0 ? (const void*)((const __half*)src0 + (size_t)t * xs)
                                : (const void*)((const float*)src0 + (size_t)t * us));
                    cpasync4(dst1 + s * (q1 < 192 ? 256 : 128),
                             p1 ? (const void*)((const __half*)src1 + (size_t)t * xs)
                                : (const void*)((const float*)src1 + (size_t)t * us));
                    cp_commit();
                }
                cp_wait<CHUNK>();
            } else {
                cp_wait<0>();
            }
        }
        __syncthreads();
        #undef GATE
    } else if (wid < 2) {
        // ---------- c-chain warps ----------
        const int ch = tid;
        const int d = dbase + ch;
        const float vf2 = -v[d] * L2E;
        const float bfz = -bb[d] * L2E;

        float c = 0.0f;
        for (int k = 0; k < NCH; ++k) {
            __syncthreads();
            const int t0 = k * CHUNK;
            float xt_c = fXT[(t0 & (RING - 1)) * 64 + ch];
            float wf_c = fmaf(fFP[(t0 & (RING - 1)) * 64 + ch], -L2E, bfz);
            #pragma unroll
            for (int i = 0; i < CHUNK; ++i) {
                float xt_n = 0.0f, wf_n = 0.0f;
                if (i + 1 < CHUNK) {
                    const int s1 = (t0 + i + 1) & (RING - 1);
                    xt_n = fXT[s1 * 64 + ch];
                    wf_n = fmaf(fFP[s1 * 64 + ch], -L2E, bfz);
                }
                const float zf = fmaf(vf2, c, wf_c);
                const float f  = rcpf(1.0f + ex2f(zf));
                c = fmaf(f, c - xt_c, xt_c);
                fC[((k & 1) * CHUNK + i) * 64 + ch] = c;
                xt_c = xt_n;  wf_c = wf_n;
            }
        }
        __syncthreads();
    } else {
        // ---------- r/readout warps (lag one chunk), publish g_sprog ----------
        const int ch = tid - 64;
        const int d = dbase + ch;
        const float vr2 = -v[DD + d] * L2E;
        const float brz = -bb[DD + d] * L2E;
        __half* xh = Xhi + (size_t)b * DD + d;
        __half* xl = Xlo + (size_t)b * DD + d;
        const int odd = ch & 1;
        const int pr = ch >> 1;

        #define RCHUNK(kk) do { \
            const int p = (kk) & 1; \
            _Pragma("unroll") \
            for (int i = 0; i < CHUNK; ++i) { \
                const int t = (kk) * CHUNK + i; \
                const int s = t & (RING - 1); \
                const float cc = fC[(p * CHUNK + i) * 64 + ch]; \
                const float rp = fRP[s * 64 + ch]; \
                const uint32_t hu = uXH[s * 32 + pr]; \
                const uint32_t lu = uXL[s * 32 + pr]; \
                const float2 hv = __half22float2(*(const __half2*)&hu); \
                const float2 lv = __half22float2(*(const __half2*)&lu); \
                const float xo = (odd ? hv.y : hv.x) + (odd ? lv.y : lv.x); \
                const float zr = fmaf(vr2, cc, fmaf(rp, -L2E, brz)); \
                const float r  = rcpf(1.0f + ex2f(zr)); \
                const float h  = fmaf(r, cc - xo, xo); \
                __half hh, hl; \
                f16split(h, hh, hl); \
                xh[(size_t)t * xs] = hh; \
                xl[(size_t)t * xs] = hl; \
            } \
            if ((kk) & 1) { \
                __threadfence(); \
                asm volatile("bar.sync 2, 64;" ::: "memory"); \
                if (tid == 64) atomicAdd(&g_sprog[(kk) >> 1], 1u); \
            } \
        } while (0)

        for (int k = 0; k < NCH; ++k) {
            __syncthreads();
            if (k == 0) continue;
            RCHUNK(k - 1);
        }
        __syncthreads();
        RCHUNK(NCH - 1);
        #undef RCHUNK
    }
}

// ---------------------------------------------------------------- mega kernel
__global__ void __launch_bounds__(256, 2)
mega(const __half* __restrict__ Wh,
     float* __restrict__ U,
     __half* __restrict__ Xhi, __half* __restrict__ Xlo,
     const float* __restrict__ sru_v, const float* __restrict__ sru_b,
     const float* __restrict__ fc_b, float* __restrict__ out) {
    extern __shared__ __align__(16) char smem_raw[];
    __shared__ unsigned s_task;

    for (;;) {
        if (threadIdx.x == 0) s_task = atomicAdd(&g_task, 1u);
        __syncthreads();
        const unsigned task = s_task;
        if (task >= NTASKS) return;

        if (task < LAY * TASKS_PER_LAYER) {
            const int L = task / TASKS_PER_LAYER;
            const int r = task % TASKS_PER_LAYER;
            if (r < 768) {
                gemm_tile(Xhi, Wh + (size_t)L * KTOT * NSRU, U, nullptr,
                          NSRU, (r / 24) * 128, (r % 24) * 128,
                          false, smem_raw, 128u * (unsigned)L);
            } else {
                sru_task(U, Xhi, Xlo,
                         sru_v + (size_t)L * 2 * DD, sru_b + (size_t)L * 2 * DD,
                         r - 768, 24u * (unsigned)(L + 1), smem_raw);
            }
        } else {
            const int fc = task - LAY * TASKS_PER_LAYER;   // 0..127
            gemm_tile(Xhi, Wh + (size_t)LAY * KTOT * NSRU, out, fc_b,
                      NTOK, (fc >> 2) * 128, (fc & 3) * 128,
                      true, smem_raw, 128u * LAY);
        }
        __syncthreads();   // reconverge + protect s_task before next pop
    }
}

// ---------------------------------------------------------------- fused prep
#define CONV_BLKS  4096
#define SPLIT_BLKS 3200
#define PREP_BLKS  (CONV_BLKS + SPLIT_BLKS + 1)

__global__ void __launch_bounds__(1024)
prep_all(const float* __restrict__ feats, const float* __restrict__ w,
         const float* __restrict__ bptr,
         __half* __restrict__ Xhi, __half* __restrict__ Xlo,
         const float* __restrict__ Wsru, const float* __restrict__ Wfc,
         __half* __restrict__ Wh,
         const int* __restrict__ lenbuf, float* outf, long long* outll,
         int rem) {
    __shared__ float s[32][33];
    const int blk = blockIdx.x;
    const int tid = threadIdx.x;

    if (blk < CONV_BLKS) {
        const int tx = tid & 31, ty = tid >> 5;
        const int bx = blk & 15, by = (blk >> 4) & 31, bz = blk >> 9;
        const int t = bx * 32 + tx;
        const int f = by * 32 + ty;
        const int b = bz;

        float acc = bptr[0];
        const float* base = feats + ((size_t)(b * CIN) * FD + f) * TD + t;
        #pragma unroll
        for (int c = 0; c < CIN; ++c)
            acc = fmaf(base[(size_t)c * FD * TD], w[c], acc);
        s[ty][tx] = fmaxf(acc, 0.0f);
        __syncthreads();

        const int t2 = bx * 32 + ty;
        const int f2 = by * 32 + tx;
        const float x = s[tx][ty];
        const size_t o = (size_t)(t2 * BB + b) * DD + f2;
        __half h, l;
        f16split(x, h, l);
        Xhi[o] = h;  Xlo[o] = l;
    } else if (blk < CONV_BLKS + SPLIT_BLKS) {
        const size_t i = (size_t)(blk - CONV_BLKS) * 1024 + tid;
        const size_t n4sru = (size_t)LAY * NSRU * KTOT / 4;
        const float4 x = (i < n4sru) ? ((const float4*)Wsru)[i]
                                     : ((const float4*)Wfc)[i - n4sru];
        __half h[4];
        h[0] = __float2half_rn(x.x);
        h[1] = __float2half_rn(x.y);
        h[2] = __float2half_rn(x.z);
        h[3] = __float2half_rn(x.w);
        ((ulonglong1*)Wh)[i] = *(ulonglong1*)h;
    } else {
        if (tid < 32) { g_prog[tid] = 0u; g_sprog[tid] = 0u; }
        if (tid == 32) g_task = 0u;
        if (tid < BB && rem > 0) {
            const bool in64 = (lenbuf[1] == 0 && lenbuf[3] == 0 &&
                               lenbuf[5] == 0 && lenbuf[7] == 0);
            const long long val = in64 ? (long long)lenbuf[2 * tid]
                                       : (long long)lenbuf[tid];
            const long long hv = val >> 1;
            if (rem >= 16)      outll[tid] = hv;
            else if (rem >= 8)  outf[tid]  = (float)hv;
        }
    }
}

// ---------------------------------------------------------------- host side
extern "C" void kernel_launch(void* const* d_in, const int* in_sizes, int n_in,
                              void* d_out, int out_size) {
    const float* feats  = (const float*)d_in[0];
    const int*   slen   = (const int*)d_in[1];
    const float* conv_w = (const float*)d_in[2];
    const float* conv_b = (const float*)d_in[3];
    const float* sru_W  = (const float*)d_in[4];
    const float* sru_v  = (const float*)d_in[5];
    const float* sru_b  = (const float*)d_in[6];
    const float* fc_w   = (const float*)d_in[7];
    const float* fc_b   = (const float*)d_in[8];

    float* Up;
    __half *Xhi, *Xlo, *Wh;
    cudaGetSymbolAddress((void**)&Xhi, g_Xhi);
    cudaGetSymbolAddress((void**)&Xlo, g_Xlo);
    cudaGetSymbolAddress((void**)&Up,  g_U);
    cudaGetSymbolAddress((void**)&Wh,  g_Wh);

    cudaFuncSetAttribute(mega,
                         cudaFuncAttributeMaxDynamicSharedMemorySize, SMEM_GEMM);

    // prep: conv + weight split + lengths tail + counter reset
    {
        const int rem = out_size - LOGITS_ELEMS;
        float* outf = (float*)d_out + LOGITS_ELEMS;
        long long* outll = (long long*)((char*)d_out + (size_t)LOGITS_ELEMS * 4);
        prep_all<<<PREP_BLKS, 1024>>>(feats, conv_w, conv_b, Xhi, Xlo,
                                      sru_W, fc_w, Wh, slen, outf, outll, rem);
    }

    // whole network: 4x(GEMM+SRU) + FC in one persistent work-queue kernel
    mega<<<MEGA_GRID, 256, SMEM_GEMM>>>(Wh, Up, Xhi, Xlo,
                                        sru_v, sru_b, fc_b, (float*)d_out);
}